// round 10
// baseline (speedup 1.0000x reference)
#include <cuda_runtime.h>
#include <cuda_bf16.h>
#include <math.h>
#include <stdint.h>

#define S 1024
#define D 1024
#define H 16
#define HD 64
#define NL 6
#define DFF 4096
#define EPS 1.1920929e-07f

// ---------------- fp32 scratch ----------------
__device__ float g_x [S*D];
__device__ float g_x0[S*D];
__device__ float g_xl[S*D];
__device__ float g_q [S*D];
__device__ float g_k [S*D];
__device__ float g_v [S*D];
__device__ float g_v1[S*D];
__device__ unsigned g_mask[S][S/32];
__device__ int g_cpad[S+1];

// ---------------- split-bf16 operand buffers (K' = 3K) ----------------
// A-side: [hi|hi|lo]   B-side: [hi|lo|hi]  -> dot = ah*bh + ah*bl + al*bh
__device__ __align__(256) __nv_bfloat16 g_wqkvb[(size_t)NL*3072*3072];
__device__ __align__(256) __nv_bfloat16 g_wob  [(size_t)NL*1024*3072];
__device__ __align__(256) __nv_bfloat16 g_wfcb [(size_t)NL*4096*3072];
__device__ __align__(256) __nv_bfloat16 g_wpb  [(size_t)NL*1024*12288];
__device__ __align__(256) __nv_bfloat16 g_ab   [(size_t)1024*3072];
__device__ __align__(256) __nv_bfloat16 g_hb   [(size_t)1024*12288];

__device__ __forceinline__ uint32_t smem_u32(const void* p) {
    uint32_t a;
    asm("{ .reg .u64 t; cvta.to.shared.u64 t, %1; cvt.u32.u64 %0, t; }" : "=r"(a) : "l"(p));
    return a;
}
__device__ __forceinline__ void split_bf16(float v, __nv_bfloat16& hi, __nv_bfloat16& lo) {
    hi = __float2bfloat16(v);
    lo = __float2bfloat16(v - __bfloat162float(hi));
}

// ================= weight conversion kernels =================
__global__ __launch_bounds__(256) void conv_kernel(const float* __restrict__ src,
                                                   __nv_bfloat16* __restrict__ dst,
                                                   int K) {   // B-side [hi|lo|hi]
    int idx = blockIdx.x * 256 + threadIdx.x;
    int K4 = K >> 2;
    int r = idx / K4, k4 = idx - r * K4;
    float4 v = ((const float4*)src)[idx];
    __nv_bfloat16 h0, h1, h2, h3, l0, l1, l2, l3;
    split_bf16(v.x, h0, l0); split_bf16(v.y, h1, l1);
    split_bf16(v.z, h2, l2); split_bf16(v.w, h3, l3);
    size_t base = (size_t)r * 3 * K + k4 * 4;
    __nv_bfloat162 H01 = __halves2bfloat162(h0, h1), H23 = __halves2bfloat162(h2, h3);
    __nv_bfloat162 L01 = __halves2bfloat162(l0, l1), L23 = __halves2bfloat162(l2, l3);
    __nv_bfloat162* p0 = (__nv_bfloat162*)(dst + base);
    __nv_bfloat162* p1 = (__nv_bfloat162*)(dst + base + K);
    __nv_bfloat162* p2 = (__nv_bfloat162*)(dst + base + 2 * K);
    p0[0] = H01; p0[1] = H23;
    p1[0] = L01; p1[1] = L23;
    p2[0] = H01; p2[1] = H23;
}

__global__ __launch_bounds__(256) void conv_qkv_kernel(const float* __restrict__ Wq,
                                                       const float* __restrict__ Wk,
                                                       const float* __restrict__ Wv) {
    int idx = blockIdx.x * 256 + threadIdx.x;
    int l = idx / (3072 * 256);
    int rem = idx - l * (3072 * 256);
    int n = rem >> 8;
    int k4 = rem & 255;
    int sel = n >> 10, nn = n & 1023;
    const float* srcm = (sel == 0) ? Wq : (sel == 1) ? Wk : Wv;
    float4 v = ((const float4*)(srcm + ((size_t)l * 1024 + nn) * 1024))[k4];
    __nv_bfloat16 h0, h1, h2, h3, l0, l1, l2, l3;
    split_bf16(v.x, h0, l0); split_bf16(v.y, h1, l1);
    split_bf16(v.z, h2, l2); split_bf16(v.w, h3, l3);
    size_t base = ((size_t)l * 3072 + n) * 3072 + k4 * 4;
    __nv_bfloat162 H01 = __halves2bfloat162(h0, h1), H23 = __halves2bfloat162(h2, h3);
    __nv_bfloat162 L01 = __halves2bfloat162(l0, l1), L23 = __halves2bfloat162(l2, l3);
    __nv_bfloat162* p0 = (__nv_bfloat162*)(g_wqkvb + base);
    __nv_bfloat162* p1 = (__nv_bfloat162*)(g_wqkvb + base + 1024);
    __nv_bfloat162* p2 = (__nv_bfloat162*)(g_wqkvb + base + 2048);
    p0[0] = H01; p0[1] = H23;
    p1[0] = L01; p1[1] = L23;
    p2[0] = H01; p2[1] = H23;
}

// ================= mma.sync bf16 GEMM =================
// C[M,N] = A[M,Kp] * B[N,Kp]^T
// mode 0: C0=acc ; 1: C0=Res+acc ; 2: C0=relu(acc)^2 ;
// 3: qkv split into C0/C1/C2 with fused v-mix ; 4: relu(acc)^2 -> bf16 split into C0 (hb)
// BM=128, BN=32*NT, BK=32, 3-stage cp.async, 8 warps (2 x 4), warp tile 64 x (8*NT).
#define A_PITCH 80
#define A_STAGE (128 * A_PITCH)

template<int NT>
__device__ __forceinline__ void fill_stage(const __nv_bfloat16* Ab, const __nv_bfloat16* Bb,
                                           int Kp, uint32_t sA, uint32_t sB, int tid) {
    const int BN = 32 * NT;
    #pragma unroll
    for (int slot = tid; slot < 512; slot += 256) {
        int row = slot >> 2, ch = slot & 3;
        uint32_t dst = sA + row * A_PITCH + ch * 16;
        const char* src = (const char*)(Ab + (size_t)row * Kp) + ch * 16;
        asm volatile("cp.async.cg.shared.global [%0], [%1], 16;" :: "r"(dst), "l"(src));
    }
    #pragma unroll
    for (int slot = tid; slot < BN * 4; slot += 256) {
        int row = slot >> 2, ch = slot & 3;
        uint32_t dst = sB + row * A_PITCH + ch * 16;
        const char* src = (const char*)(Bb + (size_t)row * Kp) + ch * 16;
        asm volatile("cp.async.cg.shared.global [%0], [%1], 16;" :: "r"(dst), "l"(src));
    }
}

template<int NT>
__global__ __launch_bounds__(256) void tc_gemm(
    const __nv_bfloat16* __restrict__ A, const __nv_bfloat16* __restrict__ B,
    const float* __restrict__ Res, float* __restrict__ C0,
    float* __restrict__ C1, float* __restrict__ C2,
    int M, int N, int Kp, int mode, const float* __restrict__ lamb, int layer)
{
    extern __shared__ __align__(128) char dyn[];
    const int BN = 32 * NT;
    const int B_STAGE = BN * A_PITCH;
    const int STAGE = A_STAGE + B_STAGE;
    const int tid = threadIdx.x;
    const int wid = tid >> 5;
    const int lane = tid & 31;
    const int warp_m = wid >> 2;
    const int warp_n = wid & 3;
    const uint32_t sb0 = smem_u32(dyn);

    const int m0 = blockIdx.y * 128, n0 = blockIdx.x * BN;
    const int NC = Kp >> 5;
    const __nv_bfloat16* Abase = A + (size_t)m0 * Kp;
    const __nv_bfloat16* Bbase = B + (size_t)n0 * Kp;

    float acc[4][NT][4];
    #pragma unroll
    for (int mt = 0; mt < 4; mt++)
        #pragma unroll
        for (int nt = 0; nt < NT; nt++)
            #pragma unroll
            for (int r = 0; r < 4; r++) acc[mt][nt][r] = 0.f;

    #pragma unroll
    for (int s = 0; s < 3; s++) {
        fill_stage<NT>(Abase + s * 32, Bbase + s * 32, Kp,
                       sb0 + s * STAGE, sb0 + s * STAGE + A_STAGE, tid);
        asm volatile("cp.async.commit_group;" ::: "memory");
    }

    const int a_row = lane & 15;
    const int a_kc  = (lane >> 4) * 16;
    const int b_row = ((lane & 16) >> 1) + (lane & 7);
    const int b_kc  = ((lane >> 3) & 1) * 16;

    for (int c = 0; c < NC; c++) {
        int st = c % 3;
        asm volatile("cp.async.wait_group 2;" ::: "memory");
        __syncthreads();

        uint32_t sA = sb0 + st * STAGE;
        uint32_t sB = sA + A_STAGE;

        #pragma unroll
        for (int ks = 0; ks < 2; ks++) {
            uint32_t a[4][4];
            #pragma unroll
            for (int mt = 0; mt < 4; mt++) {
                uint32_t addr = sA + (warp_m * 64 + mt * 16 + a_row) * A_PITCH + ks * 32 + a_kc;
                asm volatile("ldmatrix.sync.aligned.m8n8.x4.shared.b16 {%0,%1,%2,%3}, [%4];"
                    : "=r"(a[mt][0]), "=r"(a[mt][1]), "=r"(a[mt][2]), "=r"(a[mt][3]) : "r"(addr));
            }
            uint32_t b[NT][2];
            #pragma unroll
            for (int nt2 = 0; nt2 < NT / 2; nt2++) {
                uint32_t addr = sB + (warp_n * (8 * NT) + nt2 * 16 + b_row) * A_PITCH + ks * 32 + b_kc;
                asm volatile("ldmatrix.sync.aligned.m8n8.x4.shared.b16 {%0,%1,%2,%3}, [%4];"
                    : "=r"(b[nt2*2][0]), "=r"(b[nt2*2][1]), "=r"(b[nt2*2+1][0]), "=r"(b[nt2*2+1][1])
                    : "r"(addr));
            }
            #pragma unroll
            for (int mt = 0; mt < 4; mt++)
                #pragma unroll
                for (int nt = 0; nt < NT; nt++)
                    asm volatile(
                        "mma.sync.aligned.m16n8k16.row.col.f32.bf16.bf16.f32 "
                        "{%0,%1,%2,%3}, {%4,%5,%6,%7}, {%8,%9}, {%0,%1,%2,%3};"
                        : "+f"(acc[mt][nt][0]), "+f"(acc[mt][nt][1]),
                          "+f"(acc[mt][nt][2]), "+f"(acc[mt][nt][3])
                        : "r"(a[mt][0]), "r"(a[mt][1]), "r"(a[mt][2]), "r"(a[mt][3]),
                          "r"(b[nt][0]), "r"(b[nt][1]));
        }
        __syncthreads();
        if (c + 3 < NC)
            fill_stage<NT>(Abase + (c + 3) * 32, Bbase + (c + 3) * 32, Kp,
                           sb0 + st * STAGE, sb0 + st * STAGE + A_STAGE, tid);
        asm volatile("cp.async.commit_group;" ::: "memory");
    }

    const float lam = (mode == 3 && layer > 0) ? lamb[layer] : 0.f;
    const int qrow = lane >> 2;
    const int qcol = (lane & 3) * 2;
    #pragma unroll
    for (int mt = 0; mt < 4; mt++) {
        #pragma unroll
        for (int nt = 0; nt < NT; nt++) {
            int gr = m0 + warp_m * 64 + mt * 16 + qrow;
            int gc = n0 + warp_n * (8 * NT) + nt * 8 + qcol;
            #pragma unroll
            for (int half = 0; half < 2; half++) {
                int row = gr + half * 8;
                float2 v = make_float2(acc[mt][nt][half*2], acc[mt][nt][half*2+1]);
                if (mode == 1) {
                    float2 rr = *(const float2*)(Res + (size_t)row * N + gc);
                    v.x += rr.x; v.y += rr.y;
                    *(float2*)(C0 + (size_t)row * N + gc) = v;
                } else if (mode == 2) {
                    float a0 = fmaxf(v.x, 0.f), a1 = fmaxf(v.y, 0.f);
                    v.x = a0 * a0; v.y = a1 * a1;
                    *(float2*)(C0 + (size_t)row * N + gc) = v;
                } else if (mode == 3) {
                    int sel = gc >> 10, cc = gc & 1023;
                    if (sel == 2) {
                        if (layer == 0) {
                            *(float2*)(g_v1 + (size_t)row * 1024 + cc) = v;
                        } else {
                            float2 u = *(const float2*)(g_v1 + (size_t)row * 1024 + cc);
                            v.x = (1.f - lam) * v.x + lam * u.x;
                            v.y = (1.f - lam) * v.y + lam * u.y;
                        }
                        *(float2*)(C2 + (size_t)row * 1024 + cc) = v;
                    } else {
                        float* Cd = (sel == 0) ? C0 : C1;
                        *(float2*)(Cd + (size_t)row * 1024 + cc) = v;
                    }
                } else if (mode == 4) {
                    float a0 = fmaxf(v.x, 0.f), a1 = fmaxf(v.y, 0.f);
                    v.x = a0 * a0; v.y = a1 * a1;
                    __nv_bfloat16 h0, h1, l0, l1;
                    split_bf16(v.x, h0, l0); split_bf16(v.y, h1, l1);
                    __nv_bfloat16* hbp = (__nv_bfloat16*)C0;
                    size_t rb = (size_t)row * 12288;
                    *(__nv_bfloat162*)(hbp + rb + gc)        = __halves2bfloat162(h0, h1);
                    *(__nv_bfloat162*)(hbp + rb + 4096 + gc) = __halves2bfloat162(h0, h1);
                    *(__nv_bfloat162*)(hbp + rb + 8192 + gc) = __halves2bfloat162(l0, l1);
                } else {
                    *(float2*)(C0 + (size_t)row * N + gc) = v;
                }
            }
        }
    }
}

// ================= mask / norm / elementwise =================
__global__ void prefix_kernel(const int* __restrict__ levels) {
    if (blockIdx.x == 0 && threadIdx.x == 0) {
        int c = 0;
        g_cpad[0] = 0;
        for (int i = 0; i < S; i++) { c += (levels[i] == 0); g_cpad[i+1] = c; }
    }
}

__global__ void mask_kernel(const int* __restrict__ levels, const int* __restrict__ sidx) {
    int q = blockIdx.x;
    int w = threadIdx.x;
    int sq = sidx[q];
    int cq = g_cpad[q];
    unsigned bits = 0u;
    #pragma unroll
    for (int j = 0; j < 32; j++) {
        int k = w * 32 + j;
        bool ok = (k <= q) && (sidx[k] == sq);
        if (ok && (levels[k] == 0) && (cq - g_cpad[k+1] > 0)) ok = false;
        if (ok) bits |= (1u << j);
    }
    g_mask[q][w] = bits;
}

__global__ __launch_bounds__(256) void rms_kernel(const float* __restrict__ in,
                                                  float* __restrict__ out) {
    __shared__ float sred[8];
    int row = blockIdx.x;
    const float4* ip = (const float4*)(in + (size_t)row * D);
    float4* op = (float4*)(out + (size_t)row * D);
    float4 a = ip[threadIdx.x];
    float s = a.x*a.x + a.y*a.y + a.z*a.z + a.w*a.w;
    #pragma unroll
    for (int o = 16; o > 0; o >>= 1) s += __shfl_xor_sync(0xffffffffu, s, o);
    if ((threadIdx.x & 31) == 0) sred[threadIdx.x >> 5] = s;
    __syncthreads();
    if (threadIdx.x == 0) {
        float t = 0.f;
        #pragma unroll
        for (int i = 0; i < 8; i++) t += sred[i];
        sred[0] = t;
    }
    __syncthreads();
    float r = rsqrtf(sred[0] * (1.0f / (float)D) + EPS);
    a.x *= r; a.y *= r; a.z *= r; a.w *= r;
    op[threadIdx.x] = a;
}

__global__ void copy_x0_kernel() {
    int i = blockIdx.x * 256 + threadIdx.x;
    ((float4*)g_x0)[i] = ((const float4*)g_x)[i];
}

// fused: [optional lerp] -> rms -> split-bf16 A-side into g_ab ; optionally writes xl fp32
__global__ __launch_bounds__(256) void rms_conv_kernel(const float* __restrict__ lambdas,
                                                       int layer, int dolerp) {
    __shared__ float sred[8];
    int row = blockIdx.x;
    int t = threadIdx.x;
    float4 a = ((const float4*)(g_x + (size_t)row * D))[t];
    if (dolerp) {
        float l0 = lambdas[layer*2 + 0];
        float l1 = lambdas[layer*2 + 1];
        float4 b = ((const float4*)(g_x0 + (size_t)row * D))[t];
        a.x = l0*a.x + l1*b.x; a.y = l0*a.y + l1*b.y;
        a.z = l0*a.z + l1*b.z; a.w = l0*a.w + l1*b.w;
        ((float4*)(g_xl + (size_t)row * D))[t] = a;
    }
    float s = a.x*a.x + a.y*a.y + a.z*a.z + a.w*a.w;
    #pragma unroll
    for (int o = 16; o > 0; o >>= 1) s += __shfl_xor_sync(0xffffffffu, s, o);
    if ((t & 31) == 0) sred[t >> 5] = s;
    __syncthreads();
    if (t == 0) {
        float tt = 0.f;
        #pragma unroll
        for (int i = 0; i < 8; i++) tt += sred[i];
        sred[0] = tt;
    }
    __syncthreads();
    float r = rsqrtf(sred[0] * (1.0f / (float)D) + EPS);
    a.x *= r; a.y *= r; a.z *= r; a.w *= r;
    __nv_bfloat16 h0, h1, h2, h3, l0, l1, l2, l3;
    split_bf16(a.x, h0, l0); split_bf16(a.y, h1, l1);
    split_bf16(a.z, h2, l2); split_bf16(a.w, h3, l3);
    size_t base = (size_t)row * 3072 + t * 4;
    __nv_bfloat162 H01 = __halves2bfloat162(h0, h1), H23 = __halves2bfloat162(h2, h3);
    __nv_bfloat162 L01 = __halves2bfloat162(l0, l1), L23 = __halves2bfloat162(l2, l3);
    ((__nv_bfloat162*)(g_ab + base))[0] = H01; ((__nv_bfloat162*)(g_ab + base))[1] = H23;
    ((__nv_bfloat162*)(g_ab + base + 1024))[0] = H01; ((__nv_bfloat162*)(g_ab + base + 1024))[1] = H23;
    ((__nv_bfloat162*)(g_ab + base + 2048))[0] = L01; ((__nv_bfloat162*)(g_ab + base + 2048))[1] = L23;
}

__global__ __launch_bounds__(512) void qkrope_kernel() {
    int t = blockIdx.x;
    int h = threadIdx.y;
    int j = threadIdx.x;
    float inv = powf(10000.f, -(float)j / 32.f);
    float fr = (float)t * inv;
    float c = cosf(fr), sn = sinf(fr);
    #pragma unroll
    for (int which = 0; which < 2; which++) {
        float* p = (which ? g_k : g_q) + (size_t)t * D + h * HD;
        float a = p[j];
        float b = p[j + 32];
        float ss = a*a + b*b;
        #pragma unroll
        for (int o = 16; o > 0; o >>= 1) ss += __shfl_xor_sync(0xffffffffu, ss, o);
        float r = rsqrtf(ss * (1.0f/64.0f) + EPS);
        a *= r; b *= r;
        p[j]      =  a*c + b*sn;
        p[j + 32] = -a*sn + b*c;
    }
}

// ---------------- attention: 8 q x 1 head per block, 256 threads, fused y->split-bf16 ----------------
#define MQ 8
__global__ __launch_bounds__(256) void attn_kernel() {
    __shared__ float qs[MQ][HD];
    __shared__ float sc[MQ][S];
    __shared__ float red[MQ][4][HD];
    __shared__ float s_sum[MQ];

    int h  = blockIdx.y;
    int q0 = blockIdx.x * MQ;
    int tid = threadIdx.x;

    if (tid < 128) {
        int mq = tid >> 4;
        int c  = tid & 15;
        ((float4*)qs[mq])[c] = ((const float4*)(g_q + (size_t)(q0 + mq) * D + h * HD))[c];
    }
    __syncthreads();

    const float scale = 0.125f;

    // pass 1: scores (each thread handles 4 k rows)
    for (int k = tid; k < S; k += 256) {
        float4 kr[16];
        const float4* kp = (const float4*)(g_k + (size_t)k * D + h * HD);
        #pragma unroll
        for (int c = 0; c < 16; c++) kr[c] = kp[c];
        #pragma unroll
        for (int mq = 0; mq < MQ; mq++) {
            const float4* qp = (const float4*)qs[mq];
            float acc = 0.f;
            #pragma unroll
            for (int c = 0; c < 16; c++) {
                float4 qv = qp[c];
                acc += qv.x*kr[c].x + qv.y*kr[c].y + qv.z*kr[c].z + qv.w*kr[c].w;
            }
            bool ok = (g_mask[q0 + mq][k >> 5] >> (k & 31)) & 1u;
            sc[mq][k] = ok ? acc * scale : -1e30f;
        }
    }
    __syncthreads();

    // pass 2: softmax, warp w owns row mq=w
    {
        int w = tid >> 5, lane = tid & 31;
        int mq = w;
        float m = -1e30f;
        for (int k = lane; k < S; k += 32) m = fmaxf(m, sc[mq][k]);
        #pragma unroll
        for (int o = 16; o > 0; o >>= 1) m = fmaxf(m, __shfl_xor_sync(0xffffffffu, m, o));
        float ssum = 0.f;
        for (int k = lane; k < S; k += 32) {
            float e = expf(sc[mq][k] - m);
            sc[mq][k] = e;
            ssum += e;
        }
        #pragma unroll
        for (int o = 16; o > 0; o >>= 1) ssum += __shfl_xor_sync(0xffffffffu, ssum, o);
        if (lane == 0) s_sum[mq] = ssum;
    }
    __syncthreads();

    // pass 3: y = P @ V, 4 k-quarters
    {
        int d = tid & 63;
        int qtr = tid >> 6;
        float yacc[MQ];
        #pragma unroll
        for (int mq = 0; mq < MQ; mq++) yacc[mq] = 0.f;
        int kb = qtr * 256;
        for (int k = kb; k < kb + 256; k += 4) {
            float v0 = g_v[(size_t)(k+0) * D + h * HD + d];
            float v1 = g_v[(size_t)(k+1) * D + h * HD + d];
            float v2 = g_v[(size_t)(k+2) * D + h * HD + d];
            float v3 = g_v[(size_t)(k+3) * D + h * HD + d];
            #pragma unroll
            for (int mq = 0; mq < MQ; mq++) {
                float4 p = ((const float4*)sc[mq])[k >> 2];
                yacc[mq] += p.x*v0 + p.y*v1 + p.z*v2 + p.w*v3;
            }
        }
        #pragma unroll
        for (int mq = 0; mq < MQ; mq++) red[mq][qtr][d] = yacc[mq];
        __syncthreads();
        if (qtr == 0) {
            #pragma unroll
            for (int mq = 0; mq < MQ; mq++) {
                float val = (red[mq][0][d] + red[mq][1][d] + red[mq][2][d] + red[mq][3][d])
                            / s_sum[mq];
                // fused split-bf16 write into A-side buffer for the Wo GEMM
                int row = q0 + mq, c = h * HD + d;
                __nv_bfloat16 hi, lo;
                split_bf16(val, hi, lo);
                g_ab[(size_t)row * 3072 + c]        = hi;
                g_ab[(size_t)row * 3072 + 1024 + c] = hi;
                g_ab[(size_t)row * 3072 + 2048 + c] = lo;
            }
        }
    }
}

// ================= host orchestration =================
extern "C" void kernel_launch(void* const* d_in, const int* in_sizes, int n_in,
                              void* d_out, int out_size) {
    const float* xin     = (const float*)d_in[0];
    const float* Wq      = (const float*)d_in[1];
    const float* Wk      = (const float*)d_in[2];
    const float* Wv      = (const float*)d_in[3];
    const float* Wo      = (const float*)d_in[4];
    const float* lamb    = (const float*)d_in[5];
    const float* lambdas = (const float*)d_in[6];
    const float* Wfc     = (const float*)d_in[7];
    const float* Wp      = (const float*)d_in[8];
    const int*   levels  = (const int*)d_in[9];
    const int*   sample  = (const int*)d_in[10];
    float* out = (float*)d_out;

    const int SMEM4 = 3 * (128 + 128) * A_PITCH;  // 61440
    const int SMEM2 = 3 * (128 + 64)  * A_PITCH;  // 46080
    cudaFuncSetAttribute(tc_gemm<4>, cudaFuncAttributeMaxDynamicSharedMemorySize, SMEM4);
    cudaFuncSetAttribute(tc_gemm<2>, cudaFuncAttributeMaxDynamicSharedMemorySize, SMEM2);

    void *px, *pxl, *pq, *pk, *pv;
    void *pwqkvb, *pwob, *pwfcb, *pwpb, *pab, *phb;
    cudaGetSymbolAddress(&px,  g_x);
    cudaGetSymbolAddress(&pxl, g_xl);
    cudaGetSymbolAddress(&pq,  g_q);
    cudaGetSymbolAddress(&pk,  g_k);
    cudaGetSymbolAddress(&pv,  g_v);
    cudaGetSymbolAddress(&pwqkvb, g_wqkvb);
    cudaGetSymbolAddress(&pwob,   g_wob);
    cudaGetSymbolAddress(&pwfcb,  g_wfcb);
    cudaGetSymbolAddress(&pwpb,   g_wpb);
    cudaGetSymbolAddress(&pab,    g_ab);
    cudaGetSymbolAddress(&phb,    g_hb);

    const int EW_GRID = (S * D / 4) / 256;

    // weight conversions (every launch; deterministic)
    conv_qkv_kernel<<<NL * 3072 * 256 / 256, 256>>>(Wq, Wk, Wv);
    conv_kernel<<<(NL * 1024 * 1024 / 4) / 256, 256>>>(Wo,  (__nv_bfloat16*)pwob,  1024);
    conv_kernel<<<(NL * 4096 * 1024 / 4) / 256, 256>>>(Wfc, (__nv_bfloat16*)pwfcb, 1024);
    conv_kernel<<<(NL * 1024 * 4096 / 4) / 256, 256>>>(Wp,  (__nv_bfloat16*)pwpb,  4096);

    prefix_kernel<<<1, 32>>>(levels);
    mask_kernel<<<S, 32>>>(levels, sample);

    rms_kernel<<<S, 256>>>(xin, (float*)px);
    copy_x0_kernel<<<EW_GRID, 256>>>();

    for (int l = 0; l < NL; l++) {
        // xl = lerp(x, x0); ab = split(rms(xl))
        rms_conv_kernel<<<S, 256>>>(lambdas, l, 1);

        // fused QKV GEMM with fused v-mix in epilogue
        tc_gemm<4><<<dim3(3072/128, S/128), 256, SMEM4>>>(
            (const __nv_bfloat16*)pab, (const __nv_bfloat16*)pwqkvb + (size_t)l*3072*3072,
            nullptr, (float*)pq, (float*)pk, (float*)pv, S, 3072, 3072, 3, lamb, l);

        qkrope_kernel<<<S, dim3(32, 16)>>>();
        attn_kernel<<<dim3(S / MQ, H), 256>>>();   // writes g_ab (split y)

        // x = xl + y @ Wo^T   (BN=64 -> 128 CTAs)
        tc_gemm<2><<<dim3(1024/64, S/128), 256, SMEM2>>>(
            (const __nv_bfloat16*)pab, (const __nv_bfloat16*)pwob + (size_t)l*1024*3072,
            (const float*)pxl, (float*)px, nullptr, nullptr, S, 1024, 3072, 1, nullptr, 0);

        // MLP: ab = split(rms(x)) ; hb = split(relu(ab @ Wfc^T)^2) ; x += hb @ Wp^T
        rms_conv_kernel<<<S, 256>>>(nullptr, 0, 0);
        tc_gemm<4><<<dim3(4096/128, S/128), 256, SMEM4>>>(
            (const __nv_bfloat16*)pab, (const __nv_bfloat16*)pwfcb + (size_t)l*4096*3072,
            nullptr, (float*)phb, nullptr, nullptr, S, 4096, 3072, 4, nullptr, 0);
        tc_gemm<2><<<dim3(1024/64, S/128), 256, SMEM2>>>(
            (const __nv_bfloat16*)phb, (const __nv_bfloat16*)pwpb + (size_t)l*1024*12288,
            (const float*)px, (float*)px, nullptr, nullptr, S, 1024, 12288, 1, nullptr, 0);
    }

    rms_kernel<<<S, 256>>>((const float*)px, out);
}

// round 11
// speedup vs baseline: 1.5822x; 1.5822x over previous
#include <cuda_runtime.h>
#include <cuda_bf16.h>
#include <math.h>
#include <stdint.h>

#define S 1024
#define D 1024
#define H 16
#define HD 64
#define NL 6
#define DFF 4096
#define EPS 1.1920929e-07f

// ---------------- fp32 scratch ----------------
__device__ float g_x [S*D];
__device__ float g_x0[S*D];
__device__ float g_xl[S*D];
__device__ float g_q [S*D];   // QKV q ; later split-K partial 0
__device__ float g_k [S*D];   // QKV k ; later split-K partial 1
__device__ float g_v [S*D];
__device__ float g_v1[S*D];
__device__ unsigned g_mask[S][S/32];
__device__ int g_cpad[S+1];
__device__ int g_kstart[S];

// ---------------- split-bf16 operand buffers (K' = 3K) ----------------
// A-side: [hi|hi|lo]   B-side: [hi|lo|hi]  -> dot = ah*bh + ah*bl + al*bh
__device__ __align__(256) __nv_bfloat16 g_wqkvb[(size_t)NL*3072*3072];
__device__ __align__(256) __nv_bfloat16 g_wob  [(size_t)NL*1024*3072];
__device__ __align__(256) __nv_bfloat16 g_wfcb [(size_t)NL*4096*3072];
__device__ __align__(256) __nv_bfloat16 g_wpb  [(size_t)NL*1024*12288];
__device__ __align__(256) __nv_bfloat16 g_ab   [(size_t)1024*3072];
__device__ __align__(256) __nv_bfloat16 g_hb   [(size_t)1024*12288];

__device__ __forceinline__ uint32_t smem_u32(const void* p) {
    uint32_t a;
    asm("{ .reg .u64 t; cvta.to.shared.u64 t, %1; cvt.u32.u64 %0, t; }" : "=r"(a) : "l"(p));
    return a;
}
__device__ __forceinline__ void split_bf16(float v, __nv_bfloat16& hi, __nv_bfloat16& lo) {
    hi = __float2bfloat16(v);
    lo = __float2bfloat16(v - __bfloat162float(hi));
}

// ================= weight conversion kernels =================
__global__ __launch_bounds__(256) void conv_kernel(const float* __restrict__ src,
                                                   __nv_bfloat16* __restrict__ dst,
                                                   int K) {   // B-side [hi|lo|hi]
    int idx = blockIdx.x * 256 + threadIdx.x;
    int K4 = K >> 2;
    int r = idx / K4, k4 = idx - r * K4;
    float4 v = ((const float4*)src)[idx];
    __nv_bfloat16 h0, h1, h2, h3, l0, l1, l2, l3;
    split_bf16(v.x, h0, l0); split_bf16(v.y, h1, l1);
    split_bf16(v.z, h2, l2); split_bf16(v.w, h3, l3);
    size_t base = (size_t)r * 3 * K + k4 * 4;
    __nv_bfloat162 H01 = __halves2bfloat162(h0, h1), H23 = __halves2bfloat162(h2, h3);
    __nv_bfloat162 L01 = __halves2bfloat162(l0, l1), L23 = __halves2bfloat162(l2, l3);
    __nv_bfloat162* p0 = (__nv_bfloat162*)(dst + base);
    __nv_bfloat162* p1 = (__nv_bfloat162*)(dst + base + K);
    __nv_bfloat162* p2 = (__nv_bfloat162*)(dst + base + 2 * K);
    p0[0] = H01; p0[1] = H23;
    p1[0] = L01; p1[1] = L23;
    p2[0] = H01; p2[1] = H23;
}

__global__ __launch_bounds__(256) void conv_qkv_kernel(const float* __restrict__ Wq,
                                                       const float* __restrict__ Wk,
                                                       const float* __restrict__ Wv) {
    int idx = blockIdx.x * 256 + threadIdx.x;
    int l = idx / (3072 * 256);
    int rem = idx - l * (3072 * 256);
    int n = rem >> 8;
    int k4 = rem & 255;
    int sel = n >> 10, nn = n & 1023;
    const float* srcm = (sel == 0) ? Wq : (sel == 1) ? Wk : Wv;
    float4 v = ((const float4*)(srcm + ((size_t)l * 1024 + nn) * 1024))[k4];
    __nv_bfloat16 h0, h1, h2, h3, l0, l1, l2, l3;
    split_bf16(v.x, h0, l0); split_bf16(v.y, h1, l1);
    split_bf16(v.z, h2, l2); split_bf16(v.w, h3, l3);
    size_t base = ((size_t)l * 3072 + n) * 3072 + k4 * 4;
    __nv_bfloat162 H01 = __halves2bfloat162(h0, h1), H23 = __halves2bfloat162(h2, h3);
    __nv_bfloat162 L01 = __halves2bfloat162(l0, l1), L23 = __halves2bfloat162(l2, l3);
    __nv_bfloat162* p0 = (__nv_bfloat162*)(g_wqkvb + base);
    __nv_bfloat162* p1 = (__nv_bfloat162*)(g_wqkvb + base + 1024);
    __nv_bfloat162* p2 = (__nv_bfloat162*)(g_wqkvb + base + 2048);
    p0[0] = H01; p0[1] = H23;
    p1[0] = L01; p1[1] = L23;
    p2[0] = H01; p2[1] = H23;
}

// ================= mma.sync bf16 GEMM =================
// C[M,N] = A[M,Kp] * B[N,Kp]^T   (row strides ldA/ldB for split-K)
// mode 0: C0=acc ; 1: C0=Res+acc ; 3: qkv split C0/C1/C2 + fused v-mix ;
// 4: relu(acc)^2 -> bf16 split into C0 (hb layout)
// BM=128, BN=128, BK=32, 3-stage cp.async, 8 warps (2x4), warp tile 64x32.
#define A_PITCH 80
#define A_STAGE (128 * A_PITCH)
#define STAGE   (2 * A_STAGE)
#define GSMEM   (3 * STAGE)

__device__ __forceinline__ void fill_stage(const __nv_bfloat16* Ab, const __nv_bfloat16* Bb,
                                           int ldA, int ldB, uint32_t sA, uint32_t sB, int tid) {
    #pragma unroll
    for (int i = 0; i < 2; i++) {
        int slot = tid + i * 256;
        int row = slot >> 2, ch = slot & 3;
        uint32_t dst = sA + row * A_PITCH + ch * 16;
        const char* src = (const char*)(Ab + (size_t)row * ldA) + ch * 16;
        asm volatile("cp.async.cg.shared.global [%0], [%1], 16;" :: "r"(dst), "l"(src));
    }
    #pragma unroll
    for (int i = 0; i < 2; i++) {
        int slot = tid + i * 256;
        int row = slot >> 2, ch = slot & 3;
        uint32_t dst = sB + row * A_PITCH + ch * 16;
        const char* src = (const char*)(Bb + (size_t)row * ldB) + ch * 16;
        asm volatile("cp.async.cg.shared.global [%0], [%1], 16;" :: "r"(dst), "l"(src));
    }
}

__global__ __launch_bounds__(256) void tc_gemm(
    const __nv_bfloat16* __restrict__ A, const __nv_bfloat16* __restrict__ B,
    const float* __restrict__ Res, float* __restrict__ C0,
    float* __restrict__ C1, float* __restrict__ C2,
    int M, int N, int Kp, int ldA, int ldB, int mode,
    const float* __restrict__ lamb, int layer)
{
    extern __shared__ __align__(128) char dyn[];
    const int tid = threadIdx.x;
    const int wid = tid >> 5;
    const int lane = tid & 31;
    const int warp_m = wid >> 2;
    const int warp_n = wid & 3;
    const uint32_t sb0 = smem_u32(dyn);

    const int m0 = blockIdx.y * 128, n0 = blockIdx.x * 128;
    const int NC = Kp >> 5;
    const __nv_bfloat16* Abase = A + (size_t)m0 * ldA;
    const __nv_bfloat16* Bbase = B + (size_t)n0 * ldB;

    float acc[4][4][4];
    #pragma unroll
    for (int mt = 0; mt < 4; mt++)
        #pragma unroll
        for (int nt = 0; nt < 4; nt++)
            #pragma unroll
            for (int r = 0; r < 4; r++) acc[mt][nt][r] = 0.f;

    #pragma unroll
    for (int s = 0; s < 3; s++) {
        fill_stage(Abase + s * 32, Bbase + s * 32, ldA, ldB,
                   sb0 + s * STAGE, sb0 + s * STAGE + A_STAGE, tid);
        asm volatile("cp.async.commit_group;" ::: "memory");
    }

    const int a_row = lane & 15;
    const int a_kc  = (lane >> 4) * 16;
    const int b_row = ((lane & 16) >> 1) + (lane & 7);
    const int b_kc  = ((lane >> 3) & 1) * 16;

    for (int c = 0; c < NC; c++) {
        int st = c % 3;
        asm volatile("cp.async.wait_group 2;" ::: "memory");
        __syncthreads();

        uint32_t sA = sb0 + st * STAGE;
        uint32_t sB = sA + A_STAGE;

        #pragma unroll
        for (int ks = 0; ks < 2; ks++) {
            uint32_t a[4][4];
            #pragma unroll
            for (int mt = 0; mt < 4; mt++) {
                uint32_t addr = sA + (warp_m * 64 + mt * 16 + a_row) * A_PITCH + ks * 32 + a_kc;
                asm volatile("ldmatrix.sync.aligned.m8n8.x4.shared.b16 {%0,%1,%2,%3}, [%4];"
                    : "=r"(a[mt][0]), "=r"(a[mt][1]), "=r"(a[mt][2]), "=r"(a[mt][3]) : "r"(addr));
            }
            uint32_t b[4][2];
            #pragma unroll
            for (int nt2 = 0; nt2 < 2; nt2++) {
                uint32_t addr = sB + (warp_n * 32 + nt2 * 16 + b_row) * A_PITCH + ks * 32 + b_kc;
                asm volatile("ldmatrix.sync.aligned.m8n8.x4.shared.b16 {%0,%1,%2,%3}, [%4];"
                    : "=r"(b[nt2*2][0]), "=r"(b[nt2*2][1]), "=r"(b[nt2*2+1][0]), "=r"(b[nt2*2+1][1])
                    : "r"(addr));
            }
            #pragma unroll
            for (int mt = 0; mt < 4; mt++)
                #pragma unroll
                for (int nt = 0; nt < 4; nt++)
                    asm volatile(
                        "mma.sync.aligned.m16n8k16.row.col.f32.bf16.bf16.f32 "
                        "{%0,%1,%2,%3}, {%4,%5,%6,%7}, {%8,%9}, {%0,%1,%2,%3};"
                        : "+f"(acc[mt][nt][0]), "+f"(acc[mt][nt][1]),
                          "+f"(acc[mt][nt][2]), "+f"(acc[mt][nt][3])
                        : "r"(a[mt][0]), "r"(a[mt][1]), "r"(a[mt][2]), "r"(a[mt][3]),
                          "r"(b[nt][0]), "r"(b[nt][1]));
        }
        __syncthreads();
        if (c + 3 < NC)
            fill_stage(Abase + (c + 3) * 32, Bbase + (c + 3) * 32, ldA, ldB,
                       sb0 + st * STAGE, sb0 + st * STAGE + A_STAGE, tid);
        asm volatile("cp.async.commit_group;" ::: "memory");
    }

    const float lam = (mode == 3 && layer > 0) ? lamb[layer] : 0.f;
    const int qrow = lane >> 2;
    const int qcol = (lane & 3) * 2;
    #pragma unroll
    for (int mt = 0; mt < 4; mt++) {
        #pragma unroll
        for (int nt = 0; nt < 4; nt++) {
            int gr = m0 + warp_m * 64 + mt * 16 + qrow;
            int gc = n0 + warp_n * 32 + nt * 8 + qcol;
            #pragma unroll
            for (int half = 0; half < 2; half++) {
                int row = gr + half * 8;
                float2 v = make_float2(acc[mt][nt][half*2], acc[mt][nt][half*2+1]);
                if (mode == 1) {
                    float2 rr = *(const float2*)(Res + (size_t)row * N + gc);
                    v.x += rr.x; v.y += rr.y;
                    *(float2*)(C0 + (size_t)row * N + gc) = v;
                } else if (mode == 3) {
                    int sel = gc >> 10, cc = gc & 1023;
                    if (sel == 2) {
                        if (layer == 0) {
                            *(float2*)(g_v1 + (size_t)row * 1024 + cc) = v;
                        } else {
                            float2 u = *(const float2*)(g_v1 + (size_t)row * 1024 + cc);
                            v.x = (1.f - lam) * v.x + lam * u.x;
                            v.y = (1.f - lam) * v.y + lam * u.y;
                        }
                        *(float2*)(C2 + (size_t)row * 1024 + cc) = v;
                    } else {
                        float* Cd = (sel == 0) ? C0 : C1;
                        *(float2*)(Cd + (size_t)row * 1024 + cc) = v;
                    }
                } else if (mode == 4) {
                    float a0 = fmaxf(v.x, 0.f), a1 = fmaxf(v.y, 0.f);
                    v.x = a0 * a0; v.y = a1 * a1;
                    __nv_bfloat16 h0, h1, l0, l1;
                    split_bf16(v.x, h0, l0); split_bf16(v.y, h1, l1);
                    __nv_bfloat16* hbp = (__nv_bfloat16*)C0;
                    size_t rb = (size_t)row * 12288;
                    *(__nv_bfloat162*)(hbp + rb + gc)        = __halves2bfloat162(h0, h1);
                    *(__nv_bfloat162*)(hbp + rb + 4096 + gc) = __halves2bfloat162(h0, h1);
                    *(__nv_bfloat162*)(hbp + rb + 8192 + gc) = __halves2bfloat162(l0, l1);
                } else {
                    *(float2*)(C0 + (size_t)row * N + gc) = v;
                }
            }
        }
    }
}

// split-K combine: out = res + p0 + p1
__global__ void combine_kernel(const float* __restrict__ p0, const float* __restrict__ p1,
                               const float* __restrict__ res, float* __restrict__ out) {
    int i = blockIdx.x * 256 + threadIdx.x;
    float4 a = ((const float4*)p0)[i];
    float4 b = ((const float4*)p1)[i];
    float4 r = ((const float4*)res)[i];
    float4 o;
    o.x = r.x + a.x + b.x; o.y = r.y + a.y + b.y;
    o.z = r.z + a.z + b.z; o.w = r.w + a.w + b.w;
    ((float4*)out)[i] = o;
}

// ================= mask / range precompute =================
__global__ void prefix_kernel(const int* __restrict__ levels) {
    if (blockIdx.x == 0 && threadIdx.x == 0) {
        int c = 0;
        g_cpad[0] = 0;
        for (int i = 0; i < S; i++) { c += (levels[i] == 0); g_cpad[i+1] = c; }
    }
}

__global__ void mask_kernel(const int* __restrict__ levels, const int* __restrict__ sidx) {
    int q = blockIdx.x;
    int w = threadIdx.x;
    int sq = sidx[q];
    int cq = g_cpad[q];
    unsigned bits = 0u;
    #pragma unroll
    for (int j = 0; j < 32; j++) {
        int k = w * 32 + j;
        bool ok = (k <= q) && (sidx[k] == sq);
        if (ok && (levels[k] == 0) && (cq - g_cpad[k+1] > 0)) ok = false;
        if (ok) bits |= (1u << j);
    }
    g_mask[q][w] = bits;
}

// kstart[q] = first index with sample_idx == sample_idx[q]  (sample_idx sorted)
__global__ void kstart_kernel(const int* __restrict__ sidx) {
    int q = blockIdx.x * 256 + threadIdx.x;
    if (q >= S) return;
    int target = sidx[q];
    int lo = 0, hi = q;
    while (lo < hi) {
        int mid = (lo + hi) >> 1;
        if (sidx[mid] < target) lo = mid + 1; else hi = mid;
    }
    g_kstart[q] = lo;
}

// ================= norm / elementwise =================
__global__ __launch_bounds__(256) void rms_kernel(const float* __restrict__ in,
                                                  float* __restrict__ out) {
    __shared__ float sred[8];
    int row = blockIdx.x;
    const float4* ip = (const float4*)(in + (size_t)row * D);
    float4* op = (float4*)(out + (size_t)row * D);
    float4 a = ip[threadIdx.x];
    float s = a.x*a.x + a.y*a.y + a.z*a.z + a.w*a.w;
    #pragma unroll
    for (int o = 16; o > 0; o >>= 1) s += __shfl_xor_sync(0xffffffffu, s, o);
    if ((threadIdx.x & 31) == 0) sred[threadIdx.x >> 5] = s;
    __syncthreads();
    if (threadIdx.x == 0) {
        float t = 0.f;
        #pragma unroll
        for (int i = 0; i < 8; i++) t += sred[i];
        sred[0] = t;
    }
    __syncthreads();
    float r = rsqrtf(sred[0] * (1.0f / (float)D) + EPS);
    a.x *= r; a.y *= r; a.z *= r; a.w *= r;
    op[threadIdx.x] = a;
}

__global__ void copy_x0_kernel() {
    int i = blockIdx.x * 256 + threadIdx.x;
    ((float4*)g_x0)[i] = ((const float4*)g_x)[i];
}

// fused: [optional lerp] -> rms -> split-bf16 A-side into g_ab ; optionally writes xl fp32
__global__ __launch_bounds__(256) void rms_conv_kernel(const float* __restrict__ lambdas,
                                                       int layer, int dolerp) {
    __shared__ float sred[8];
    int row = blockIdx.x;
    int t = threadIdx.x;
    float4 a = ((const float4*)(g_x + (size_t)row * D))[t];
    if (dolerp) {
        float l0 = lambdas[layer*2 + 0];
        float l1 = lambdas[layer*2 + 1];
        float4 b = ((const float4*)(g_x0 + (size_t)row * D))[t];
        a.x = l0*a.x + l1*b.x; a.y = l0*a.y + l1*b.y;
        a.z = l0*a.z + l1*b.z; a.w = l0*a.w + l1*b.w;
        ((float4*)(g_xl + (size_t)row * D))[t] = a;
    }
    float s = a.x*a.x + a.y*a.y + a.z*a.z + a.w*a.w;
    #pragma unroll
    for (int o = 16; o > 0; o >>= 1) s += __shfl_xor_sync(0xffffffffu, s, o);
    if ((t & 31) == 0) sred[t >> 5] = s;
    __syncthreads();
    if (t == 0) {
        float tt = 0.f;
        #pragma unroll
        for (int i = 0; i < 8; i++) tt += sred[i];
        sred[0] = tt;
    }
    __syncthreads();
    float r = rsqrtf(sred[0] * (1.0f / (float)D) + EPS);
    a.x *= r; a.y *= r; a.z *= r; a.w *= r;
    __nv_bfloat16 h0, h1, h2, h3, l0, l1, l2, l3;
    split_bf16(a.x, h0, l0); split_bf16(a.y, h1, l1);
    split_bf16(a.z, h2, l2); split_bf16(a.w, h3, l3);
    size_t base = (size_t)row * 3072 + t * 4;
    __nv_bfloat162 H01 = __halves2bfloat162(h0, h1), H23 = __halves2bfloat162(h2, h3);
    __nv_bfloat162 L01 = __halves2bfloat162(l0, l1), L23 = __halves2bfloat162(l2, l3);
    ((__nv_bfloat162*)(g_ab + base))[0] = H01; ((__nv_bfloat162*)(g_ab + base))[1] = H23;
    ((__nv_bfloat162*)(g_ab + base + 1024))[0] = H01; ((__nv_bfloat162*)(g_ab + base + 1024))[1] = H23;
    ((__nv_bfloat162*)(g_ab + base + 2048))[0] = L01; ((__nv_bfloat162*)(g_ab + base + 2048))[1] = L23;
}

__global__ __launch_bounds__(512) void qkrope_kernel() {
    int t = blockIdx.x;
    int h = threadIdx.y;
    int j = threadIdx.x;
    float inv = powf(10000.f, -(float)j / 32.f);
    float fr = (float)t * inv;
    float c = cosf(fr), sn = sinf(fr);
    #pragma unroll
    for (int which = 0; which < 2; which++) {
        float* p = (which ? g_k : g_q) + (size_t)t * D + h * HD;
        float a = p[j];
        float b = p[j + 32];
        float ss = a*a + b*b;
        #pragma unroll
        for (int o = 16; o > 0; o >>= 1) ss += __shfl_xor_sync(0xffffffffu, ss, o);
        float r = rsqrtf(ss * (1.0f/64.0f) + EPS);
        a *= r; b *= r;
        p[j]      =  a*c + b*sn;
        p[j + 32] = -a*sn + b*c;
    }
}

// ---------------- attention: range-limited (sorted sample_idx), 8 q x 1 head / block ----------------
#define MQ 8
#define SCPAD 1028
__global__ __launch_bounds__(256) void attn_kernel() {
    __shared__ float qs[MQ][HD];
    __shared__ float sc[MQ][SCPAD];
    __shared__ float red[MQ][4][HD];
    __shared__ float s_sum[MQ];

    int h  = blockIdx.y;
    int q0 = blockIdx.x * MQ;
    int tid = threadIdx.x;

    if (tid < 128) {
        int mq = tid >> 4;
        int c  = tid & 15;
        ((float4*)qs[mq])[c] = ((const float4*)(g_q + (size_t)(q0 + mq) * D + h * HD))[c];
    }
    __syncthreads();

    // valid k range for this block: [kstart[q0], q0+MQ-1]  (exact mask applied inside)
    const int kmax = q0 + MQ - 1;
    const int k0   = g_kstart[q0] & ~3;              // float4-aligned start
    const int klen = kmax - k0 + 1;
    const int kpad = k0 + ((klen + 3) & ~3);         // 4-aligned end (exclusive)

    // scale * log2(e): softmax via exp2
    const float SCL = 0.125f * 1.4426950408889634f;

    // pass 1: scores over range (+ zero tail padding)
    for (int k = k0 + tid; k < kpad; k += 256) {
        if (k > kmax) {
            #pragma unroll
            for (int mq = 0; mq < MQ; mq++) sc[mq][k] = 0.f;   // probability-domain 0
            continue;
        }
        float4 kr[16];
        const float4* kp = (const float4*)(g_k + (size_t)k * D + h * HD);
        #pragma unroll
        for (int c = 0; c < 16; c++) kr[c] = kp[c];
        unsigned mword_cache = 0;
        #pragma unroll
        for (int mq = 0; mq < MQ; mq++) {
            const float4* qp = (const float4*)qs[mq];
            float acc = 0.f;
            #pragma unroll
            for (int c = 0; c < 16; c++) {
                float4 qv = qp[c];
                acc += qv.x*kr[c].x + qv.y*kr[c].y + qv.z*kr[c].z + qv.w*kr[c].w;
            }
            (void)mword_cache;
            bool ok = (g_mask[q0 + mq][k >> 5] >> (k & 31)) & 1u;
            sc[mq][k] = ok ? acc * SCL : -1e30f;
        }
    }
    __syncthreads();

    // pass 2: softmax over [k0, kmax]; warp w owns row mq=w
    {
        int w = tid >> 5, lane = tid & 31;
        int mq = w;
        float m = -1e30f;
        for (int k = k0 + lane; k <= kmax; k += 32) m = fmaxf(m, sc[mq][k]);
        #pragma unroll
        for (int o = 16; o > 0; o >>= 1) m = fmaxf(m, __shfl_xor_sync(0xffffffffu, m, o));
        float ssum = 0.f;
        for (int k = k0 + lane; k <= kmax; k += 32) {
            float e = exp2f(sc[mq][k] - m);
            sc[mq][k] = e;
            ssum += e;
        }
        #pragma unroll
        for (int o = 16; o > 0; o >>= 1) ssum += __shfl_xor_sync(0xffffffffu, ssum, o);
        if (lane == 0) s_sum[mq] = ssum;
    }
    __syncthreads();

    // pass 3: y = P @ V over range, 4 k-quarters
    {
        int d = tid & 63;
        int qtr = tid >> 6;
        float yacc[MQ];
        #pragma unroll
        for (int mq = 0; mq < MQ; mq++) yacc[mq] = 0.f;
        int qlen = ((klen + 15) >> 4) << 2;          // multiple of 4, 4*qlen covers range
        int kb = k0 + qtr * qlen;
        int ke = kb + qlen;
        for (int k = kb; k < ke && k < kpad; k += 4) {
            float v0 = g_v[(size_t)(k+0) * D + h * HD + d];
            float v1 = g_v[(size_t)(k+1) * D + h * HD + d];
            float v2 = g_v[(size_t)(k+2) * D + h * HD + d];
            float v3 = g_v[(size_t)(k+3) * D + h * HD + d];
            #pragma unroll
            for (int mq = 0; mq < MQ; mq++) {
                float4 p = ((const float4*)sc[mq])[k >> 2];
                yacc[mq] += p.x*v0 + p.y*v1 + p.z*v2 + p.w*v3;
            }
        }
        #pragma unroll
        for (int mq = 0; mq < MQ; mq++) red[mq][qtr][d] = yacc[mq];
        __syncthreads();
        if (qtr == 0) {
            #pragma unroll
            for (int mq = 0; mq < MQ; mq++) {
                float val = (red[mq][0][d] + red[mq][1][d] + red[mq][2][d] + red[mq][3][d])
                            / s_sum[mq];
                int row = q0 + mq, c = h * HD + d;
                __nv_bfloat16 hi, lo;
                split_bf16(val, hi, lo);
                g_ab[(size_t)row * 3072 + c]        = hi;
                g_ab[(size_t)row * 3072 + 1024 + c] = hi;
                g_ab[(size_t)row * 3072 + 2048 + c] = lo;
            }
        }
    }
}

// NOTE: pass-3 reads g_v for k in [kpad-3, kmax+3] region only where k < kpad <= S+3 is
// impossible since kmax <= S-1 and kpad <= kmax+3... guarded: kpad = k0+((klen+3)&~3) and
// loop clamps k < kpad; rows k in (kmax, kpad) have sc==0 so their v-loads are harmless;
// kpad <= S is guaranteed when kmax = S-1 gives klen = S-k0, kpad = k0+round4(klen) <= S+3.
// To be safe g_v has no row past S-1 accessed because kpad-1 <= kmax+3 <= S+2... we clamp
// via the padding rows existing only when klen%4 != 0; k0 is 4-aligned and kmax=q0+7 so
// klen = kmax-k0+1 ≡ 0 (mod 4) always (both 4-aligned endpoints). Hence kpad == kmax+1 <= S.

// ================= host orchestration =================
extern "C" void kernel_launch(void* const* d_in, const int* in_sizes, int n_in,
                              void* d_out, int out_size) {
    const float* xin     = (const float*)d_in[0];
    const float* Wq      = (const float*)d_in[1];
    const float* Wk      = (const float*)d_in[2];
    const float* Wv      = (const float*)d_in[3];
    const float* Wo      = (const float*)d_in[4];
    const float* lamb    = (const float*)d_in[5];
    const float* lambdas = (const float*)d_in[6];
    const float* Wfc     = (const float*)d_in[7];
    const float* Wp      = (const float*)d_in[8];
    const int*   levels  = (const int*)d_in[9];
    const int*   sample  = (const int*)d_in[10];
    float* out = (float*)d_out;

    cudaFuncSetAttribute(tc_gemm, cudaFuncAttributeMaxDynamicSharedMemorySize, GSMEM);

    void *px, *pxl, *pq, *pk, *pv;
    void *pwqkvb, *pwob, *pwfcb, *pwpb, *pab, *phb;
    cudaGetSymbolAddress(&px,  g_x);
    cudaGetSymbolAddress(&pxl, g_xl);
    cudaGetSymbolAddress(&pq,  g_q);
    cudaGetSymbolAddress(&pk,  g_k);
    cudaGetSymbolAddress(&pv,  g_v);
    cudaGetSymbolAddress(&pwqkvb, g_wqkvb);
    cudaGetSymbolAddress(&pwob,   g_wob);
    cudaGetSymbolAddress(&pwfcb,  g_wfcb);
    cudaGetSymbolAddress(&pwpb,   g_wpb);
    cudaGetSymbolAddress(&pab,    g_ab);
    cudaGetSymbolAddress(&phb,    g_hb);

    const int EW_GRID = (S * D / 4) / 256;

    // weight conversions (every launch; deterministic)
    conv_qkv_kernel<<<NL * 3072 * 256 / 256, 256>>>(Wq, Wk, Wv);
    conv_kernel<<<(NL * 1024 * 1024 / 4) / 256, 256>>>(Wo,  (__nv_bfloat16*)pwob,  1024);
    conv_kernel<<<(NL * 4096 * 1024 / 4) / 256, 256>>>(Wfc, (__nv_bfloat16*)pwfcb, 1024);
    conv_kernel<<<(NL * 1024 * 4096 / 4) / 256, 256>>>(Wp,  (__nv_bfloat16*)pwpb,  4096);

    prefix_kernel<<<1, 32>>>(levels);
    mask_kernel<<<S, 32>>>(levels, sample);
    kstart_kernel<<<(S + 255) / 256, 256>>>(sample);

    rms_kernel<<<S, 256>>>(xin, (float*)px);
    copy_x0_kernel<<<EW_GRID, 256>>>();

    for (int l = 0; l < NL; l++) {
        // xl = lerp(x, x0); ab = split(rms(xl))
        rms_conv_kernel<<<S, 256>>>(lambdas, l, 1);

        // fused QKV GEMM with fused v-mix in epilogue (BN=128, 192 CTAs)
        tc_gemm<<<dim3(3072/128, S/128), 256, GSMEM>>>(
            (const __nv_bfloat16*)pab, (const __nv_bfloat16*)pwqkvb + (size_t)l*3072*3072,
            nullptr, (float*)pq, (float*)pk, (float*)pv, S, 3072, 3072, 3072, 3072, 3, lamb, l);

        qkrope_kernel<<<S, dim3(32, 16)>>>();
        attn_kernel<<<dim3(S / MQ, H), 256>>>();   // writes g_ab (split y)

        // x = xl + y @ Wo^T : split-K=2 (partials in g_q/g_k) + combine
        tc_gemm<<<dim3(8, 8), 256, GSMEM>>>(
            (const __nv_bfloat16*)pab, (const __nv_bfloat16*)pwob + (size_t)l*1024*3072,
            nullptr, (float*)pq, nullptr, nullptr, S, 1024, 1536, 3072, 3072, 0, nullptr, 0);
        tc_gemm<<<dim3(8, 8), 256, GSMEM>>>(
            (const __nv_bfloat16*)pab + 1536, (const __nv_bfloat16*)pwob + (size_t)l*1024*3072 + 1536,
            nullptr, (float*)pk, nullptr, nullptr, S, 1024, 1536, 3072, 3072, 0, nullptr, 0);
        combine_kernel<<<EW_GRID, 256>>>((const float*)pq, (const float*)pk,
                                         (const float*)pxl, (float*)px);

        // MLP: ab = split(rms(x)) ; hb = split(relu(ab @ Wfc^T)^2) ; x += hb @ Wp^T
        rms_conv_kernel<<<S, 256>>>(nullptr, 0, 0);
        tc_gemm<<<dim3(4096/128, S/128), 256, GSMEM>>>(
            (const __nv_bfloat16*)pab, (const __nv_bfloat16*)pwfcb + (size_t)l*4096*3072,
            nullptr, (float*)phb, nullptr, nullptr, S, 4096, 3072, 3072, 3072, 4, nullptr, 0);
        // Wp split-K=2
        tc_gemm<<<dim3(8, 8), 256, GSMEM>>>(
            (const __nv_bfloat16*)phb, (const __nv_bfloat16*)pwpb + (size_t)l*1024*12288,
            nullptr, (float*)pq, nullptr, nullptr, S, 1024, 6144, 12288, 12288, 0, nullptr, 0);
        tc_gemm<<<dim3(8, 8), 256, GSMEM>>>(
            (const __nv_bfloat16*)phb + 6144, (const __nv_bfloat16*)pwpb + (size_t)l*1024*12288 + 6144,
            nullptr, (float*)pk, nullptr, nullptr, S, 1024, 6144, 12288, 12288, 0, nullptr, 0);
        combine_kernel<<<EW_GRID, 256>>>((const float*)pq, (const float*)pk,
                                         (const float*)px, (float*)px);
    }

    rms_kernel<<<S, 256>>>((const float*)px, out);
}

// round 14
// speedup vs baseline: 2.0464x; 1.2934x over previous
#include <cuda_runtime.h>
#include <cuda_bf16.h>
#include <math.h>
#include <stdint.h>

#define S 1024
#define D 1024
#define H 16
#define HD 64
#define NL 6
#define DFF 4096
#define EPS 1.1920929e-07f

// ---------------- fp32 scratch ----------------
__device__ float g_x [S*D];
__device__ float g_x0[S*D];
__device__ float g_xl[S*D];
__device__ float g_q [S*D];   // QKV q ; later split-K partial 0
__device__ float g_k [S*D];   // QKV k ; later split-K partial 1
__device__ float g_v [S*D];
__device__ float g_v1[S*D];
__device__ unsigned g_mask[S][S/32];
__device__ int g_cpad[S+1];
__device__ int g_kstart[S];

// ---------------- split-bf16 operand buffers (K' = 3K) ----------------
// A-side: [hi|hi|lo]   B-side: [hi|lo|hi]  -> dot = ah*bh + ah*bl + al*bh
__device__ __align__(256) __nv_bfloat16 g_wqkvb[(size_t)NL*3072*3072];
__device__ __align__(256) __nv_bfloat16 g_wob  [(size_t)NL*1024*3072];
__device__ __align__(256) __nv_bfloat16 g_wfcb [(size_t)NL*4096*3072];
__device__ __align__(256) __nv_bfloat16 g_wpb  [(size_t)NL*1024*12288];
__device__ __align__(256) __nv_bfloat16 g_ab   [(size_t)1024*3072];
__device__ __align__(256) __nv_bfloat16 g_hb   [(size_t)1024*12288];

__device__ __forceinline__ uint32_t smem_u32(const void* p) {
    uint32_t a;
    asm("{ .reg .u64 t; cvta.to.shared.u64 t, %1; cvt.u32.u64 %0, t; }" : "=r"(a) : "l"(p));
    return a;
}
__device__ __forceinline__ void split_bf16(float v, __nv_bfloat16& hi, __nv_bfloat16& lo) {
    hi = __float2bfloat16(v);
    lo = __float2bfloat16(v - __bfloat162float(hi));
}

// ================= weight conversion kernels =================
__global__ __launch_bounds__(256) void conv_kernel(const float* __restrict__ src,
                                                   __nv_bfloat16* __restrict__ dst,
                                                   int K) {   // B-side [hi|lo|hi]
    int idx = blockIdx.x * 256 + threadIdx.x;
    int K4 = K >> 2;
    int r = idx / K4, k4 = idx - r * K4;
    float4 v = ((const float4*)src)[idx];
    __nv_bfloat16 h0, h1, h2, h3, l0, l1, l2, l3;
    split_bf16(v.x, h0, l0); split_bf16(v.y, h1, l1);
    split_bf16(v.z, h2, l2); split_bf16(v.w, h3, l3);
    size_t base = (size_t)r * 3 * K + k4 * 4;
    __nv_bfloat162 H01 = __halves2bfloat162(h0, h1), H23 = __halves2bfloat162(h2, h3);
    __nv_bfloat162 L01 = __halves2bfloat162(l0, l1), L23 = __halves2bfloat162(l2, l3);
    __nv_bfloat162* p0 = (__nv_bfloat162*)(dst + base);
    __nv_bfloat162* p1 = (__nv_bfloat162*)(dst + base + K);
    __nv_bfloat162* p2 = (__nv_bfloat162*)(dst + base + 2 * K);
    p0[0] = H01; p0[1] = H23;
    p1[0] = L01; p1[1] = L23;
    p2[0] = H01; p2[1] = H23;
}

__global__ __launch_bounds__(256) void conv_qkv_kernel(const float* __restrict__ Wq,
                                                       const float* __restrict__ Wk,
                                                       const float* __restrict__ Wv) {
    int idx = blockIdx.x * 256 + threadIdx.x;
    int l = idx / (3072 * 256);
    int rem = idx - l * (3072 * 256);
    int n = rem >> 8;
    int k4 = rem & 255;
    int sel = n >> 10, nn = n & 1023;
    const float* srcm = (sel == 0) ? Wq : (sel == 1) ? Wk : Wv;
    float4 v = ((const float4*)(srcm + ((size_t)l * 1024 + nn) * 1024))[k4];
    __nv_bfloat16 h0, h1, h2, h3, l0, l1, l2, l3;
    split_bf16(v.x, h0, l0); split_bf16(v.y, h1, l1);
    split_bf16(v.z, h2, l2); split_bf16(v.w, h3, l3);
    size_t base = ((size_t)l * 3072 + n) * 3072 + k4 * 4;
    __nv_bfloat162 H01 = __halves2bfloat162(h0, h1), H23 = __halves2bfloat162(h2, h3);
    __nv_bfloat162 L01 = __halves2bfloat162(l0, l1), L23 = __halves2bfloat162(l2, l3);
    __nv_bfloat162* p0 = (__nv_bfloat162*)(g_wqkvb + base);
    __nv_bfloat162* p1 = (__nv_bfloat162*)(g_wqkvb + base + 1024);
    __nv_bfloat162* p2 = (__nv_bfloat162*)(g_wqkvb + base + 2048);
    p0[0] = H01; p0[1] = H23;
    p1[0] = L01; p1[1] = L23;
    p2[0] = H01; p2[1] = H23;
}

// ================= mma.sync bf16 GEMM =================
// C[M,N] = A[M,Kp] * B[N,Kp]^T  (ldA/ldB row strides; blockIdx.z selects K-half)
// mode 0: partial, z=0 -> C0, z=1 -> C1 ; 3: qkv split C0/C1/C2 + fused v-mix ;
// 4: relu(acc)^2 -> bf16 split into C0 (hb layout)
// BM=128, BN=128, BK=32, 3-stage cp.async, 8 warps (2x4), warp tile 64x32.
#define A_PITCH 80
#define A_STAGE (128 * A_PITCH)
#define STAGE   (2 * A_STAGE)
#define GSMEM   (3 * STAGE)

__device__ __forceinline__ void fill_stage(const __nv_bfloat16* Ab, const __nv_bfloat16* Bb,
                                           int ldA, int ldB, uint32_t sA, uint32_t sB, int tid) {
    #pragma unroll
    for (int i = 0; i < 2; i++) {
        int slot = tid + i * 256;
        int row = slot >> 2, ch = slot & 3;
        uint32_t dst = sA + row * A_PITCH + ch * 16;
        const char* src = (const char*)(Ab + (size_t)row * ldA) + ch * 16;
        asm volatile("cp.async.cg.shared.global [%0], [%1], 16;" :: "r"(dst), "l"(src));
    }
    #pragma unroll
    for (int i = 0; i < 2; i++) {
        int slot = tid + i * 256;
        int row = slot >> 2, ch = slot & 3;
        uint32_t dst = sB + row * A_PITCH + ch * 16;
        const char* src = (const char*)(Bb + (size_t)row * ldB) + ch * 16;
        asm volatile("cp.async.cg.shared.global [%0], [%1], 16;" :: "r"(dst), "l"(src));
    }
}

__global__ __launch_bounds__(256) void tc_gemm(
    const __nv_bfloat16* __restrict__ A, const __nv_bfloat16* __restrict__ B,
    float* __restrict__ C0, float* __restrict__ C1, float* __restrict__ C2,
    int M, int N, int Kp, int ldA, int ldB, int Koff, int mode,
    const float* __restrict__ lamb, int layer)
{
    extern __shared__ __align__(128) char dyn[];
    const int tid = threadIdx.x;
    const int wid = tid >> 5;
    const int lane = tid & 31;
    const int warp_m = wid >> 2;
    const int warp_n = wid & 3;
    const uint32_t sb0 = smem_u32(dyn);
    const int z = blockIdx.z;

    A += (size_t)z * Koff;
    B += (size_t)z * Koff;

    const int m0 = blockIdx.y * 128, n0 = blockIdx.x * 128;
    const int NC = Kp >> 5;
    const __nv_bfloat16* Abase = A + (size_t)m0 * ldA;
    const __nv_bfloat16* Bbase = B + (size_t)n0 * ldB;

    float acc[4][4][4];
    #pragma unroll
    for (int mt = 0; mt < 4; mt++)
        #pragma unroll
        for (int nt = 0; nt < 4; nt++)
            #pragma unroll
            for (int r = 0; r < 4; r++) acc[mt][nt][r] = 0.f;

    #pragma unroll
    for (int s = 0; s < 3; s++) {
        fill_stage(Abase + s * 32, Bbase + s * 32, ldA, ldB,
                   sb0 + s * STAGE, sb0 + s * STAGE + A_STAGE, tid);
        asm volatile("cp.async.commit_group;" ::: "memory");
    }

    const int a_row = lane & 15;
    const int a_kc  = (lane >> 4) * 16;
    const int b_row = ((lane & 16) >> 1) + (lane & 7);
    const int b_kc  = ((lane >> 3) & 1) * 16;

    for (int c = 0; c < NC; c++) {
        int st = c % 3;
        asm volatile("cp.async.wait_group 2;" ::: "memory");
        __syncthreads();

        uint32_t sA = sb0 + st * STAGE;
        uint32_t sB = sA + A_STAGE;

        #pragma unroll
        for (int ks = 0; ks < 2; ks++) {
            uint32_t a[4][4];
            #pragma unroll
            for (int mt = 0; mt < 4; mt++) {
                uint32_t addr = sA + (warp_m * 64 + mt * 16 + a_row) * A_PITCH + ks * 32 + a_kc;
                asm volatile("ldmatrix.sync.aligned.m8n8.x4.shared.b16 {%0,%1,%2,%3}, [%4];"
                    : "=r"(a[mt][0]), "=r"(a[mt][1]), "=r"(a[mt][2]), "=r"(a[mt][3]) : "r"(addr));
            }
            uint32_t b[4][2];
            #pragma unroll
            for (int nt2 = 0; nt2 < 2; nt2++) {
                uint32_t addr = sB + (warp_n * 32 + nt2 * 16 + b_row) * A_PITCH + ks * 32 + b_kc;
                asm volatile("ldmatrix.sync.aligned.m8n8.x4.shared.b16 {%0,%1,%2,%3}, [%4];"
                    : "=r"(b[nt2*2][0]), "=r"(b[nt2*2][1]), "=r"(b[nt2*2+1][0]), "=r"(b[nt2*2+1][1])
                    : "r"(addr));
            }
            #pragma unroll
            for (int mt = 0; mt < 4; mt++)
                #pragma unroll
                for (int nt = 0; nt < 4; nt++)
                    asm volatile(
                        "mma.sync.aligned.m16n8k16.row.col.f32.bf16.bf16.f32 "
                        "{%0,%1,%2,%3}, {%4,%5,%6,%7}, {%8,%9}, {%0,%1,%2,%3};"
                        : "+f"(acc[mt][nt][0]), "+f"(acc[mt][nt][1]),
                          "+f"(acc[mt][nt][2]), "+f"(acc[mt][nt][3])
                        : "r"(a[mt][0]), "r"(a[mt][1]), "r"(a[mt][2]), "r"(a[mt][3]),
                          "r"(b[nt][0]), "r"(b[nt][1]));
        }
        __syncthreads();
        if (c + 3 < NC)
            fill_stage(Abase + (c + 3) * 32, Bbase + (c + 3) * 32, ldA, ldB,
                       sb0 + st * STAGE, sb0 + st * STAGE + A_STAGE, tid);
        asm volatile("cp.async.commit_group;" ::: "memory");
    }

    const float lam = (mode == 3 && layer > 0) ? lamb[layer] : 0.f;
    const int qrow = lane >> 2;
    const int qcol = (lane & 3) * 2;
    #pragma unroll
    for (int mt = 0; mt < 4; mt++) {
        #pragma unroll
        for (int nt = 0; nt < 4; nt++) {
            int gr = m0 + warp_m * 64 + mt * 16 + qrow;
            int gc = n0 + warp_n * 32 + nt * 8 + qcol;
            #pragma unroll
            for (int half = 0; half < 2; half++) {
                int row = gr + half * 8;
                float2 v = make_float2(acc[mt][nt][half*2], acc[mt][nt][half*2+1]);
                if (mode == 3) {
                    int sel = gc >> 10, cc = gc & 1023;
                    if (sel == 2) {
                        if (layer == 0) {
                            *(float2*)(g_v1 + (size_t)row * 1024 + cc) = v;
                        } else {
                            float2 u = *(const float2*)(g_v1 + (size_t)row * 1024 + cc);
                            v.x = (1.f - lam) * v.x + lam * u.x;
                            v.y = (1.f - lam) * v.y + lam * u.y;
                        }
                        *(float2*)(C2 + (size_t)row * 1024 + cc) = v;
                    } else {
                        float* Cd = (sel == 0) ? C0 : C1;
                        *(float2*)(Cd + (size_t)row * 1024 + cc) = v;
                    }
                } else if (mode == 4) {
                    float a0 = fmaxf(v.x, 0.f), a1 = fmaxf(v.y, 0.f);
                    v.x = a0 * a0; v.y = a1 * a1;
                    __nv_bfloat16 h0, h1, l0, l1;
                    split_bf16(v.x, h0, l0); split_bf16(v.y, h1, l1);
                    __nv_bfloat16* hbp = (__nv_bfloat16*)C0;
                    size_t rb = (size_t)row * 12288;
                    *(__nv_bfloat162*)(hbp + rb + gc)        = __halves2bfloat162(h0, h1);
                    *(__nv_bfloat162*)(hbp + rb + 4096 + gc) = __halves2bfloat162(h0, h1);
                    *(__nv_bfloat162*)(hbp + rb + 8192 + gc) = __halves2bfloat162(l0, l1);
                } else {
                    float* out = z ? C1 : C0;
                    *(float2*)(out + (size_t)row * N + gc) = v;
                }
            }
        }
    }
}

// ================= mask / range precompute =================
__global__ void prefix_kernel(const int* __restrict__ levels) {
    if (blockIdx.x == 0 && threadIdx.x == 0) {
        int c = 0;
        g_cpad[0] = 0;
        for (int i = 0; i < S; i++) { c += (levels[i] == 0); g_cpad[i+1] = c; }
    }
}

__global__ void mask_kernel(const int* __restrict__ levels, const int* __restrict__ sidx) {
    int q = blockIdx.x;
    int w = threadIdx.x;
    int sq = sidx[q];
    int cq = g_cpad[q];
    unsigned bits = 0u;
    #pragma unroll
    for (int j = 0; j < 32; j++) {
        int k = w * 32 + j;
        bool ok = (k <= q) && (sidx[k] == sq);
        if (ok && (levels[k] == 0) && (cq - g_cpad[k+1] > 0)) ok = false;
        if (ok) bits |= (1u << j);
    }
    g_mask[q][w] = bits;
}

__global__ void kstart_kernel(const int* __restrict__ sidx) {
    int q = blockIdx.x * 256 + threadIdx.x;
    if (q >= S) return;
    int target = sidx[q];
    int lo = 0, hi = q;
    while (lo < hi) {
        int mid = (lo + hi) >> 1;
        if (sidx[mid] < target) lo = mid + 1; else hi = mid;
    }
    g_kstart[q] = lo;
}

// ================= fused norm / combine kernels =================
// initial: g_x = g_x0 = rms(xin)
__global__ __launch_bounds__(256) void rms_init_kernel(const float* __restrict__ in) {
    __shared__ float sred[8];
    int row = blockIdx.x;
    float4 a = ((const float4*)(in + (size_t)row * D))[threadIdx.x];
    float s = a.x*a.x + a.y*a.y + a.z*a.z + a.w*a.w;
    #pragma unroll
    for (int o = 16; o > 0; o >>= 1) s += __shfl_xor_sync(0xffffffffu, s, o);
    if ((threadIdx.x & 31) == 0) sred[threadIdx.x >> 5] = s;
    __syncthreads();
    if (threadIdx.x == 0) {
        float t = 0.f;
        #pragma unroll
        for (int i = 0; i < 8; i++) t += sred[i];
        sred[0] = t;
    }
    __syncthreads();
    float r = rsqrtf(sred[0] * (1.0f / (float)D) + EPS);
    a.x *= r; a.y *= r; a.z *= r; a.w *= r;
    ((float4*)(g_x  + (size_t)row * D))[threadIdx.x] = a;
    ((float4*)(g_x0 + (size_t)row * D))[threadIdx.x] = a;
}

__device__ __forceinline__ void write_ab_split(int row, int t, float4 a) {
    __nv_bfloat16 h0, h1, h2, h3, l0, l1, l2, l3;
    split_bf16(a.x, h0, l0); split_bf16(a.y, h1, l1);
    split_bf16(a.z, h2, l2); split_bf16(a.w, h3, l3);
    size_t base = (size_t)row * 3072 + t * 4;
    __nv_bfloat162 H01 = __halves2bfloat162(h0, h1), H23 = __halves2bfloat162(h2, h3);
    __nv_bfloat162 L01 = __halves2bfloat162(l0, l1), L23 = __halves2bfloat162(l2, l3);
    ((__nv_bfloat162*)(g_ab + base))[0] = H01; ((__nv_bfloat162*)(g_ab + base))[1] = H23;
    ((__nv_bfloat162*)(g_ab + base + 1024))[0] = H01; ((__nv_bfloat162*)(g_ab + base + 1024))[1] = H23;
    ((__nv_bfloat162*)(g_ab + base + 2048))[0] = L01; ((__nv_bfloat162*)(g_ab + base + 2048))[1] = L23;
}

__device__ __forceinline__ float block_rsqrt_mean_sq(float4 a, float* sred, int t) {
    float s = a.x*a.x + a.y*a.y + a.z*a.z + a.w*a.w;
    #pragma unroll
    for (int o = 16; o > 0; o >>= 1) s += __shfl_xor_sync(0xffffffffu, s, o);
    if ((t & 31) == 0) sred[t >> 5] = s;
    __syncthreads();
    if (t == 0) {
        float tt = 0.f;
        #pragma unroll
        for (int i = 0; i < 8; i++) tt += sred[i];
        sred[0] = tt;
    }
    __syncthreads();
    return rsqrtf(sred[0] * (1.0f / (float)D) + EPS);
}

// layer top: [x = q+k+x (if combine)] ; xl = l0*x + l1*x0 ; ab = split(rms(xl))
__global__ __launch_bounds__(256) void fused_top_kernel(const float* __restrict__ lambdas,
                                                        int layer, int docombine) {
    __shared__ float sred[8];
    int row = blockIdx.x;
    int t = threadIdx.x;
    size_t off = (size_t)row * D;
    float4 xv = ((const float4*)(g_x + off))[t];
    if (docombine) {
        float4 p0 = ((const float4*)(g_q + off))[t];
        float4 p1 = ((const float4*)(g_k + off))[t];
        xv.x += p0.x + p1.x; xv.y += p0.y + p1.y;
        xv.z += p0.z + p1.z; xv.w += p0.w + p1.w;
        ((float4*)(g_x + off))[t] = xv;
    }
    float l0 = lambdas[layer*2 + 0];
    float l1 = lambdas[layer*2 + 1];
    float4 x0v = ((const float4*)(g_x0 + off))[t];
    float4 a;
    a.x = l0*xv.x + l1*x0v.x; a.y = l0*xv.y + l1*x0v.y;
    a.z = l0*xv.z + l1*x0v.z; a.w = l0*xv.w + l1*x0v.w;
    ((float4*)(g_xl + off))[t] = a;
    float r = block_rsqrt_mean_sq(a, sred, t);
    a.x *= r; a.y *= r; a.z *= r; a.w *= r;
    write_ab_split(row, t, a);
}

// after Wo split-K: x = q+k+xl ; ab = split(rms(x))
__global__ __launch_bounds__(256) void fused_mid_kernel() {
    __shared__ float sred[8];
    int row = blockIdx.x;
    int t = threadIdx.x;
    size_t off = (size_t)row * D;
    float4 p0 = ((const float4*)(g_q  + off))[t];
    float4 p1 = ((const float4*)(g_k  + off))[t];
    float4 rr = ((const float4*)(g_xl + off))[t];
    float4 xv;
    xv.x = rr.x + p0.x + p1.x; xv.y = rr.y + p0.y + p1.y;
    xv.z = rr.z + p0.z + p1.z; xv.w = rr.w + p0.w + p1.w;
    ((float4*)(g_x + off))[t] = xv;
    float r = block_rsqrt_mean_sq(xv, sred, t);
    xv.x *= r; xv.y *= r; xv.z *= r; xv.w *= r;
    write_ab_split(row, t, xv);
}

// final: out = rms(q+k+x)
__global__ __launch_bounds__(256) void final_kernel(float* __restrict__ out) {
    __shared__ float sred[8];
    int row = blockIdx.x;
    int t = threadIdx.x;
    size_t off = (size_t)row * D;
    float4 p0 = ((const float4*)(g_q + off))[t];
    float4 p1 = ((const float4*)(g_k + off))[t];
    float4 rr = ((const float4*)(g_x + off))[t];
    float4 xv;
    xv.x = rr.x + p0.x + p1.x; xv.y = rr.y + p0.y + p1.y;
    xv.z = rr.z + p0.z + p1.z; xv.w = rr.w + p0.w + p1.w;
    float r = block_rsqrt_mean_sq(xv, sred, t);
    xv.x *= r; xv.y *= r; xv.z *= r; xv.w *= r;
    ((float4*)(out + off))[t] = xv;
}

__global__ __launch_bounds__(512) void qkrope_kernel() {
    int t = blockIdx.x;
    int h = threadIdx.y;
    int j = threadIdx.x;
    float inv = powf(10000.f, -(float)j / 32.f);
    float fr = (float)t * inv;
    float c = cosf(fr), sn = sinf(fr);
    #pragma unroll
    for (int which = 0; which < 2; which++) {
        float* p = (which ? g_k : g_q) + (size_t)t * D + h * HD;
        float a = p[j];
        float b = p[j + 32];
        float ss = a*a + b*b;
        #pragma unroll
        for (int o = 16; o > 0; o >>= 1) ss += __shfl_xor_sync(0xffffffffu, ss, o);
        float r = rsqrtf(ss * (1.0f/64.0f) + EPS);
        a *= r; b *= r;
        p[j]      =  a*c + b*sn;
        p[j + 32] = -a*sn + b*c;
    }
}

// ---------------- attention: range-limited, 8 q x 1 head / block ----------------
#define MQ 8
#define SCPAD 1028
__global__ __launch_bounds__(256) void attn_kernel() {
    __shared__ float qs[MQ][HD];
    __shared__ float sc[MQ][SCPAD];
    __shared__ float red[MQ][4][HD];
    __shared__ float s_sum[MQ];

    int h  = blockIdx.y;
    int q0 = blockIdx.x * MQ;
    int tid = threadIdx.x;

    if (tid < 128) {
        int mq = tid >> 4;
        int c  = tid & 15;
        ((float4*)qs[mq])[c] = ((const float4*)(g_q + (size_t)(q0 + mq) * D + h * HD))[c];
    }
    __syncthreads();

    const int kmax = q0 + MQ - 1;
    const int k0   = g_kstart[q0] & ~3;
    const int klen = kmax - k0 + 1;          // multiple of 4
    const int kpad = k0 + klen;              // == kmax+1

    const float SCL = 0.125f * 1.4426950408889634f;

    for (int k = k0 + tid; k < kpad; k += 256) {
        float4 kr[16];
        const float4* kp = (const float4*)(g_k + (size_t)k * D + h * HD);
        #pragma unroll
        for (int c = 0; c < 16; c++) kr[c] = kp[c];
        #pragma unroll
        for (int mq = 0; mq < MQ; mq++) {
            const float4* qp = (const float4*)qs[mq];
            float acc = 0.f;
            #pragma unroll
            for (int c = 0; c < 16; c++) {
                float4 qv = qp[c];
                acc += qv.x*kr[c].x + qv.y*kr[c].y + qv.z*kr[c].z + qv.w*kr[c].w;
            }
            bool ok = (g_mask[q0 + mq][k >> 5] >> (k & 31)) & 1u;
            sc[mq][k] = ok ? acc * SCL : -1e30f;
        }
    }
    __syncthreads();

    {
        int w = tid >> 5, lane = tid & 31;
        int mq = w;
        float m = -1e30f;
        for (int k = k0 + lane; k <= kmax; k += 32) m = fmaxf(m, sc[mq][k]);
        #pragma unroll
        for (int o = 16; o > 0; o >>= 1) m = fmaxf(m, __shfl_xor_sync(0xffffffffu, m, o));
        float ssum = 0.f;
        for (int k = k0 + lane; k <= kmax; k += 32) {
            float e = exp2f(sc[mq][k] - m);
            sc[mq][k] = e;
            ssum += e;
        }
        #pragma unroll
        for (int o = 16; o > 0; o >>= 1) ssum += __shfl_xor_sync(0xffffffffu, ssum, o);
        if (lane == 0) s_sum[mq] = ssum;
    }
    __syncthreads();

    {
        int d = tid & 63;
        int qtr = tid >> 6;
        float yacc[MQ];
        #pragma unroll
        for (int mq = 0; mq < MQ; mq++) yacc[mq] = 0.f;
        int qlen = ((klen + 15) >> 4) << 2;
        int kb = k0 + qtr * qlen;
        int ke = kb + qlen;
        for (int k = kb; k < ke && k < kpad; k += 4) {
            float v0 = g_v[(size_t)(k+0) * D + h * HD + d];
            float v1 = g_v[(size_t)(k+1) * D + h * HD + d];
            float v2 = g_v[(size_t)(k+2) * D + h * HD + d];
            float v3 = g_v[(size_t)(k+3) * D + h * HD + d];
            #pragma unroll
            for (int mq = 0; mq < MQ; mq++) {
                float4 p = ((const float4*)sc[mq])[k >> 2];
                yacc[mq] += p.x*v0 + p.y*v1 + p.z*v2 + p.w*v3;
            }
        }
        #pragma unroll
        for (int mq = 0; mq < MQ; mq++) red[mq][qtr][d] = yacc[mq];
        __syncthreads();
        if (qtr == 0) {
            #pragma unroll
            for (int mq = 0; mq < MQ; mq++) {
                float val = (red[mq][0][d] + red[mq][1][d] + red[mq][2][d] + red[mq][3][d])
                            / s_sum[mq];
                int row = q0 + mq, c = h * HD + d;
                __nv_bfloat16 hi, lo;
                split_bf16(val, hi, lo);
                g_ab[(size_t)row * 3072 + c]        = hi;
                g_ab[(size_t)row * 3072 + 1024 + c] = hi;
                g_ab[(size_t)row * 3072 + 2048 + c] = lo;
            }
        }
    }
}

// ================= host orchestration =================
extern "C" void kernel_launch(void* const* d_in, const int* in_sizes, int n_in,
                              void* d_out, int out_size) {
    const float* xin     = (const float*)d_in[0];
    const float* Wq      = (const float*)d_in[1];
    const float* Wk      = (const float*)d_in[2];
    const float* Wv      = (const float*)d_in[3];
    const float* Wo      = (const float*)d_in[4];
    const float* lamb    = (const float*)d_in[5];
    const float* lambdas = (const float*)d_in[6];
    const float* Wfc     = (const float*)d_in[7];
    const float* Wp      = (const float*)d_in[8];
    const int*   levels  = (const int*)d_in[9];
    const int*   sample  = (const int*)d_in[10];
    float* out = (float*)d_out;

    cudaFuncSetAttribute(tc_gemm, cudaFuncAttributeMaxDynamicSharedMemorySize, GSMEM);

    void *pq, *pk, *pv;
    void *pwqkvb, *pwob, *pwfcb, *pwpb, *pab, *phb;
    cudaGetSymbolAddress(&pq,  g_q);
    cudaGetSymbolAddress(&pk,  g_k);
    cudaGetSymbolAddress(&pv,  g_v);
    cudaGetSymbolAddress(&pwqkvb, g_wqkvb);
    cudaGetSymbolAddress(&pwob,   g_wob);
    cudaGetSymbolAddress(&pwfcb,  g_wfcb);
    cudaGetSymbolAddress(&pwpb,   g_wpb);
    cudaGetSymbolAddress(&pab,    g_ab);
    cudaGetSymbolAddress(&phb,    g_hb);

    // weight conversions (every launch; deterministic)
    conv_qkv_kernel<<<NL * 3072 * 256 / 256, 256>>>(Wq, Wk, Wv);
    conv_kernel<<<(NL * 1024 * 1024 / 4) / 256, 256>>>(Wo,  (__nv_bfloat16*)pwob,  1024);
    conv_kernel<<<(NL * 4096 * 1024 / 4) / 256, 256>>>(Wfc, (__nv_bfloat16*)pwfcb, 1024);
    conv_kernel<<<(NL * 1024 * 4096 / 4) / 256, 256>>>(Wp,  (__nv_bfloat16*)pwpb,  4096);

    prefix_kernel<<<1, 32>>>(levels);
    mask_kernel<<<S, 32>>>(levels, sample);
    kstart_kernel<<<(S + 255) / 256, 256>>>(sample);

    rms_init_kernel<<<S, 256>>>(xin);

    for (int l = 0; l < NL; l++) {
        // [combine Wp partials if l>0] + lerp + rms + split -> ab
        fused_top_kernel<<<S, 256>>>(lambdas, l, l > 0 ? 1 : 0);

        // fused QKV GEMM with fused v-mix in epilogue (192 CTAs)
        tc_gemm<<<dim3(3072/128, S/128, 1), 256, GSMEM>>>(
            (const __nv_bfloat16*)pab, (const __nv_bfloat16*)pwqkvb + (size_t)l*3072*3072,
            (float*)pq, (float*)pk, (float*)pv, S, 3072, 3072, 3072, 3072, 0, 3, lamb, l);

        qkrope_kernel<<<S, dim3(32, 16)>>>();
        attn_kernel<<<dim3(S / MQ, H), 256>>>();   // writes g_ab (split y)

        // y @ Wo^T : split-K=2 merged in one launch (gridDim.z=2 -> 128 CTAs)
        tc_gemm<<<dim3(8, 8, 2), 256, GSMEM>>>(
            (const __nv_bfloat16*)pab, (const __nv_bfloat16*)pwob + (size_t)l*1024*3072,
            (float*)pq, (float*)pk, nullptr, S, 1024, 1536, 3072, 3072, 1536, 0, nullptr, 0);

        // x = xl + partials ; ab = split(rms(x))
        fused_mid_kernel<<<S, 256>>>();

        // hb = split(relu(ab @ Wfc^T)^2)
        tc_gemm<<<dim3(4096/128, S/128, 1), 256, GSMEM>>>(
            (const __nv_bfloat16*)pab, (const __nv_bfloat16*)pwfcb + (size_t)l*4096*3072,
            (float*)phb, nullptr, nullptr, S, 4096, 3072, 3072, 3072, 0, 4, nullptr, 0);

        // hb @ Wp^T : split-K=2 merged
        tc_gemm<<<dim3(8, 8, 2), 256, GSMEM>>>(
            (const __nv_bfloat16*)phb, (const __nv_bfloat16*)pwpb + (size_t)l*1024*12288,
            (float*)pq, (float*)pk, nullptr, S, 1024, 6144, 12288, 12288, 6144, 0, nullptr, 0);
    }

    // out = rms(x + Wp partials)
    final_kernel<<<S, 256>>>(out);
}

// round 15
// speedup vs baseline: 2.2784x; 1.1133x over previous
#include <cuda_runtime.h>
#include <cuda_bf16.h>
#include <math.h>
#include <stdint.h>

#define S 1024
#define D 1024
#define H 16
#define HD 64
#define NL 6
#define DFF 4096
#define EPS 1.1920929e-07f

// ---------------- fp32 scratch ----------------
__device__ float g_x [S*D];
__device__ float g_x0[S*D];
__device__ float g_xl[S*D];
__device__ float g_q [S*D];   // QKV q ; later split-K partial 0
__device__ float g_k [S*D];   // QKV k ; later split-K partial 1
__device__ float g_v [S*D];
__device__ float g_v1[S*D];
__device__ unsigned g_mask[S][S/32];
__device__ int g_cpad[S+1];
__device__ int g_kstart[S];
__device__ float g_ropec[S*32];
__device__ float g_ropes[S*32];

// ---------------- split-bf16 operand buffers (K' = 3K) ----------------
// A-side: [hi|hi|lo]   B-side: [hi|lo|hi]  -> dot = ah*bh + ah*bl + al*bh
__device__ __align__(256) __nv_bfloat16 g_wqkvb[(size_t)NL*3072*3072];
__device__ __align__(256) __nv_bfloat16 g_wob  [(size_t)NL*1024*3072];
__device__ __align__(256) __nv_bfloat16 g_wfcb [(size_t)NL*4096*3072];
__device__ __align__(256) __nv_bfloat16 g_wpb  [(size_t)NL*1024*12288];
__device__ __align__(256) __nv_bfloat16 g_ab   [(size_t)1024*3072];
__device__ __align__(256) __nv_bfloat16 g_hb   [(size_t)1024*12288];

__device__ __forceinline__ uint32_t smem_u32(const void* p) {
    uint32_t a;
    asm("{ .reg .u64 t; cvta.to.shared.u64 t, %1; cvt.u32.u64 %0, t; }" : "=r"(a) : "l"(p));
    return a;
}
__device__ __forceinline__ void split_bf16(float v, __nv_bfloat16& hi, __nv_bfloat16& lo) {
    hi = __float2bfloat16(v);
    lo = __float2bfloat16(v - __bfloat162float(hi));
}

// ================= weight conversion kernels =================
__global__ __launch_bounds__(256) void conv_kernel(const float* __restrict__ src,
                                                   __nv_bfloat16* __restrict__ dst,
                                                   int K) {   // B-side [hi|lo|hi]
    int idx = blockIdx.x * 256 + threadIdx.x;
    int K4 = K >> 2;
    int r = idx / K4, k4 = idx - r * K4;
    float4 v = ((const float4*)src)[idx];
    __nv_bfloat16 h0, h1, h2, h3, l0, l1, l2, l3;
    split_bf16(v.x, h0, l0); split_bf16(v.y, h1, l1);
    split_bf16(v.z, h2, l2); split_bf16(v.w, h3, l3);
    size_t base = (size_t)r * 3 * K + k4 * 4;
    __nv_bfloat162 H01 = __halves2bfloat162(h0, h1), H23 = __halves2bfloat162(h2, h3);
    __nv_bfloat162 L01 = __halves2bfloat162(l0, l1), L23 = __halves2bfloat162(l2, l3);
    __nv_bfloat162* p0 = (__nv_bfloat162*)(dst + base);
    __nv_bfloat162* p1 = (__nv_bfloat162*)(dst + base + K);
    __nv_bfloat162* p2 = (__nv_bfloat162*)(dst + base + 2 * K);
    p0[0] = H01; p0[1] = H23;
    p1[0] = L01; p1[1] = L23;
    p2[0] = H01; p2[1] = H23;
}

__global__ __launch_bounds__(256) void conv_qkv_kernel(const float* __restrict__ Wq,
                                                       const float* __restrict__ Wk,
                                                       const float* __restrict__ Wv) {
    int idx = blockIdx.x * 256 + threadIdx.x;
    int l = idx / (3072 * 256);
    int rem = idx - l * (3072 * 256);
    int n = rem >> 8;
    int k4 = rem & 255;
    int sel = n >> 10, nn = n & 1023;
    const float* srcm = (sel == 0) ? Wq : (sel == 1) ? Wk : Wv;
    float4 v = ((const float4*)(srcm + ((size_t)l * 1024 + nn) * 1024))[k4];
    __nv_bfloat16 h0, h1, h2, h3, l0, l1, l2, l3;
    split_bf16(v.x, h0, l0); split_bf16(v.y, h1, l1);
    split_bf16(v.z, h2, l2); split_bf16(v.w, h3, l3);
    size_t base = ((size_t)l * 3072 + n) * 3072 + k4 * 4;
    __nv_bfloat162 H01 = __halves2bfloat162(h0, h1), H23 = __halves2bfloat162(h2, h3);
    __nv_bfloat162 L01 = __halves2bfloat162(l0, l1), L23 = __halves2bfloat162(l2, l3);
    __nv_bfloat162* p0 = (__nv_bfloat162*)(g_wqkvb + base);
    __nv_bfloat162* p1 = (__nv_bfloat162*)(g_wqkvb + base + 1024);
    __nv_bfloat162* p2 = (__nv_bfloat162*)(g_wqkvb + base + 2048);
    p0[0] = H01; p0[1] = H23;
    p1[0] = L01; p1[1] = L23;
    p2[0] = H01; p2[1] = H23;
}

// ================= mma.sync bf16 GEMM =================
// C[M,N] = A[M,Kp] * B[N,Kp]^T  (ldA/ldB row strides; blockIdx.z selects K-half)
// mode 0: partial, z=0 -> C0, z=1 -> C1 ; 3: qkv split C0/C1/C2 + fused v-mix ;
// 4: relu(acc)^2 -> bf16 split into C0 (hb layout)
// BM=128, BN=128, BK=32, 3-stage cp.async, 8 warps (2x4), warp tile 64x32.
// __launch_bounds__(256, 2): 2 CTAs/SM -> single-wave grids + cross-CTA latency hiding.
#define A_PITCH 80
#define A_STAGE (128 * A_PITCH)
#define STAGE   (2 * A_STAGE)
#define GSMEM   (3 * STAGE)

__device__ __forceinline__ void fill_stage(const __nv_bfloat16* Ab, const __nv_bfloat16* Bb,
                                           int ldA, int ldB, uint32_t sA, uint32_t sB, int tid) {
    #pragma unroll
    for (int i = 0; i < 2; i++) {
        int slot = tid + i * 256;
        int row = slot >> 2, ch = slot & 3;
        uint32_t dst = sA + row * A_PITCH + ch * 16;
        const char* src = (const char*)(Ab + (size_t)row * ldA) + ch * 16;
        asm volatile("cp.async.cg.shared.global [%0], [%1], 16;" :: "r"(dst), "l"(src));
    }
    #pragma unroll
    for (int i = 0; i < 2; i++) {
        int slot = tid + i * 256;
        int row = slot >> 2, ch = slot & 3;
        uint32_t dst = sB + row * A_PITCH + ch * 16;
        const char* src = (const char*)(Bb + (size_t)row * ldB) + ch * 16;
        asm volatile("cp.async.cg.shared.global [%0], [%1], 16;" :: "r"(dst), "l"(src));
    }
}

__global__ __launch_bounds__(256, 2) void tc_gemm(
    const __nv_bfloat16* __restrict__ A, const __nv_bfloat16* __restrict__ B,
    float* __restrict__ C0, float* __restrict__ C1, float* __restrict__ C2,
    int M, int N, int Kp, int ldA, int ldB, int Koff, int mode,
    const float* __restrict__ lamb, int layer)
{
    extern __shared__ __align__(128) char dyn[];
    const int tid = threadIdx.x;
    const int wid = tid >> 5;
    const int lane = tid & 31;
    const int warp_m = wid >> 2;
    const int warp_n = wid & 3;
    const uint32_t sb0 = smem_u32(dyn);
    const int z = blockIdx.z;

    A += (size_t)z * Koff;
    B += (size_t)z * Koff;

    const int m0 = blockIdx.y * 128, n0 = blockIdx.x * 128;
    const int NC = Kp >> 5;
    const __nv_bfloat16* Abase = A + (size_t)m0 * ldA;
    const __nv_bfloat16* Bbase = B + (size_t)n0 * ldB;

    float acc[4][4][4];
    #pragma unroll
    for (int mt = 0; mt < 4; mt++)
        #pragma unroll
        for (int nt = 0; nt < 4; nt++)
            #pragma unroll
            for (int r = 0; r < 4; r++) acc[mt][nt][r] = 0.f;

    #pragma unroll
    for (int s = 0; s < 3; s++) {
        fill_stage(Abase + s * 32, Bbase + s * 32, ldA, ldB,
                   sb0 + s * STAGE, sb0 + s * STAGE + A_STAGE, tid);
        asm volatile("cp.async.commit_group;" ::: "memory");
    }

    const int a_row = lane & 15;
    const int a_kc  = (lane >> 4) * 16;
    const int b_row = ((lane & 16) >> 1) + (lane & 7);
    const int b_kc  = ((lane >> 3) & 1) * 16;

    for (int c = 0; c < NC; c++) {
        int st = c % 3;
        asm volatile("cp.async.wait_group 2;" ::: "memory");
        __syncthreads();

        uint32_t sA = sb0 + st * STAGE;
        uint32_t sB = sA + A_STAGE;

        #pragma unroll
        for (int ks = 0; ks < 2; ks++) {
            uint32_t a[4][4];
            #pragma unroll
            for (int mt = 0; mt < 4; mt++) {
                uint32_t addr = sA + (warp_m * 64 + mt * 16 + a_row) * A_PITCH + ks * 32 + a_kc;
                asm volatile("ldmatrix.sync.aligned.m8n8.x4.shared.b16 {%0,%1,%2,%3}, [%4];"
                    : "=r"(a[mt][0]), "=r"(a[mt][1]), "=r"(a[mt][2]), "=r"(a[mt][3]) : "r"(addr));
            }
            uint32_t b[4][2];
            #pragma unroll
            for (int nt2 = 0; nt2 < 2; nt2++) {
                uint32_t addr = sB + (warp_n * 32 + nt2 * 16 + b_row) * A_PITCH + ks * 32 + b_kc;
                asm volatile("ldmatrix.sync.aligned.m8n8.x4.shared.b16 {%0,%1,%2,%3}, [%4];"
                    : "=r"(b[nt2*2][0]), "=r"(b[nt2*2][1]), "=r"(b[nt2*2+1][0]), "=r"(b[nt2*2+1][1])
                    : "r"(addr));
            }
            #pragma unroll
            for (int mt = 0; mt < 4; mt++)
                #pragma unroll
                for (int nt = 0; nt < 4; nt++)
                    asm volatile(
                        "mma.sync.aligned.m16n8k16.row.col.f32.bf16.bf16.f32 "
                        "{%0,%1,%2,%3}, {%4,%5,%6,%7}, {%8,%9}, {%0,%1,%2,%3};"
                        : "+f"(acc[mt][nt][0]), "+f"(acc[mt][nt][1]),
                          "+f"(acc[mt][nt][2]), "+f"(acc[mt][nt][3])
                        : "r"(a[mt][0]), "r"(a[mt][1]), "r"(a[mt][2]), "r"(a[mt][3]),
                          "r"(b[nt][0]), "r"(b[nt][1]));
        }
        __syncthreads();
        if (c + 3 < NC)
            fill_stage(Abase + (c + 3) * 32, Bbase + (c + 3) * 32, ldA, ldB,
                       sb0 + st * STAGE, sb0 + st * STAGE + A_STAGE, tid);
        asm volatile("cp.async.commit_group;" ::: "memory");
    }

    const float lam = (mode == 3 && layer > 0) ? lamb[layer] : 0.f;
    const int qrow = lane >> 2;
    const int qcol = (lane & 3) * 2;
    #pragma unroll
    for (int mt = 0; mt < 4; mt++) {
        #pragma unroll
        for (int nt = 0; nt < 4; nt++) {
            int gr = m0 + warp_m * 64 + mt * 16 + qrow;
            int gc = n0 + warp_n * 32 + nt * 8 + qcol;
            #pragma unroll
            for (int half = 0; half < 2; half++) {
                int row = gr + half * 8;
                float2 v = make_float2(acc[mt][nt][half*2], acc[mt][nt][half*2+1]);
                if (mode == 3) {
                    int sel = gc >> 10, cc = gc & 1023;
                    if (sel == 2) {
                        if (layer == 0) {
                            *(float2*)(g_v1 + (size_t)row * 1024 + cc) = v;
                        } else {
                            float2 u = *(const float2*)(g_v1 + (size_t)row * 1024 + cc);
                            v.x = (1.f - lam) * v.x + lam * u.x;
                            v.y = (1.f - lam) * v.y + lam * u.y;
                        }
                        *(float2*)(C2 + (size_t)row * 1024 + cc) = v;
                    } else {
                        float* Cd = (sel == 0) ? C0 : C1;
                        *(float2*)(Cd + (size_t)row * 1024 + cc) = v;
                    }
                } else if (mode == 4) {
                    float a0 = fmaxf(v.x, 0.f), a1 = fmaxf(v.y, 0.f);
                    v.x = a0 * a0; v.y = a1 * a1;
                    __nv_bfloat16 h0, h1, l0, l1;
                    split_bf16(v.x, h0, l0); split_bf16(v.y, h1, l1);
                    __nv_bfloat16* hbp = (__nv_bfloat16*)C0;
                    size_t rb = (size_t)row * 12288;
                    *(__nv_bfloat162*)(hbp + rb + gc)        = __halves2bfloat162(h0, h1);
                    *(__nv_bfloat162*)(hbp + rb + 4096 + gc) = __halves2bfloat162(h0, h1);
                    *(__nv_bfloat162*)(hbp + rb + 8192 + gc) = __halves2bfloat162(l0, l1);
                } else {
                    float* out = z ? C1 : C0;
                    *(float2*)(out + (size_t)row * N + gc) = v;
                }
            }
        }
    }
}

// ================= mask / range / rope precompute =================
__global__ void prefix_kernel(const int* __restrict__ levels) {
    if (blockIdx.x == 0 && threadIdx.x == 0) {
        int c = 0;
        g_cpad[0] = 0;
        for (int i = 0; i < S; i++) { c += (levels[i] == 0); g_cpad[i+1] = c; }
    }
}

__global__ void mask_kernel(const int* __restrict__ levels, const int* __restrict__ sidx) {
    int q = blockIdx.x;
    int w = threadIdx.x;
    int sq = sidx[q];
    int cq = g_cpad[q];
    unsigned bits = 0u;
    #pragma unroll
    for (int j = 0; j < 32; j++) {
        int k = w * 32 + j;
        bool ok = (k <= q) && (sidx[k] == sq);
        if (ok && (levels[k] == 0) && (cq - g_cpad[k+1] > 0)) ok = false;
        if (ok) bits |= (1u << j);
    }
    g_mask[q][w] = bits;
}

__global__ void kstart_kernel(const int* __restrict__ sidx) {
    int q = blockIdx.x * 256 + threadIdx.x;
    if (q >= S) return;
    int target = sidx[q];
    int lo = 0, hi = q;
    while (lo < hi) {
        int mid = (lo + hi) >> 1;
        if (sidx[mid] < target) lo = mid + 1; else hi = mid;
    }
    g_kstart[q] = lo;
}

// rope table: cos/sin of t * 10000^(-j/32) for t in [0,S), j in [0,32)
__global__ void rope_table_kernel() {
    int t = blockIdx.x;
    int j = threadIdx.x;
    float inv = powf(10000.f, -(float)j / 32.f);
    float fr = (float)t * inv;
    g_ropec[t * 32 + j] = cosf(fr);
    g_ropes[t * 32 + j] = sinf(fr);
}

// ================= fused norm / combine kernels =================
__global__ __launch_bounds__(256) void rms_init_kernel(const float* __restrict__ in) {
    __shared__ float sred[8];
    int row = blockIdx.x;
    float4 a = ((const float4*)(in + (size_t)row * D))[threadIdx.x];
    float s = a.x*a.x + a.y*a.y + a.z*a.z + a.w*a.w;
    #pragma unroll
    for (int o = 16; o > 0; o >>= 1) s += __shfl_xor_sync(0xffffffffu, s, o);
    if ((threadIdx.x & 31) == 0) sred[threadIdx.x >> 5] = s;
    __syncthreads();
    if (threadIdx.x == 0) {
        float t = 0.f;
        #pragma unroll
        for (int i = 0; i < 8; i++) t += sred[i];
        sred[0] = t;
    }
    __syncthreads();
    float r = rsqrtf(sred[0] * (1.0f / (float)D) + EPS);
    a.x *= r; a.y *= r; a.z *= r; a.w *= r;
    ((float4*)(g_x  + (size_t)row * D))[threadIdx.x] = a;
    ((float4*)(g_x0 + (size_t)row * D))[threadIdx.x] = a;
}

__device__ __forceinline__ void write_ab_split(int row, int t, float4 a) {
    __nv_bfloat16 h0, h1, h2, h3, l0, l1, l2, l3;
    split_bf16(a.x, h0, l0); split_bf16(a.y, h1, l1);
    split_bf16(a.z, h2, l2); split_bf16(a.w, h3, l3);
    size_t base = (size_t)row * 3072 + t * 4;
    __nv_bfloat162 H01 = __halves2bfloat162(h0, h1), H23 = __halves2bfloat162(h2, h3);
    __nv_bfloat162 L01 = __halves2bfloat162(l0, l1), L23 = __halves2bfloat162(l2, l3);
    ((__nv_bfloat162*)(g_ab + base))[0] = H01; ((__nv_bfloat162*)(g_ab + base))[1] = H23;
    ((__nv_bfloat162*)(g_ab + base + 1024))[0] = H01; ((__nv_bfloat162*)(g_ab + base + 1024))[1] = H23;
    ((__nv_bfloat162*)(g_ab + base + 2048))[0] = L01; ((__nv_bfloat162*)(g_ab + base + 2048))[1] = L23;
}

__device__ __forceinline__ float block_rsqrt_mean_sq(float4 a, float* sred, int t) {
    float s = a.x*a.x + a.y*a.y + a.z*a.z + a.w*a.w;
    #pragma unroll
    for (int o = 16; o > 0; o >>= 1) s += __shfl_xor_sync(0xffffffffu, s, o);
    if ((t & 31) == 0) sred[t >> 5] = s;
    __syncthreads();
    if (t == 0) {
        float tt = 0.f;
        #pragma unroll
        for (int i = 0; i < 8; i++) tt += sred[i];
        sred[0] = tt;
    }
    __syncthreads();
    return rsqrtf(sred[0] * (1.0f / (float)D) + EPS);
}

// layer top: [x = q+k+x (if combine)] ; xl = l0*x + l1*x0 ; ab = split(rms(xl))
__global__ __launch_bounds__(256) void fused_top_kernel(const float* __restrict__ lambdas,
                                                        int layer, int docombine) {
    __shared__ float sred[8];
    int row = blockIdx.x;
    int t = threadIdx.x;
    size_t off = (size_t)row * D;
    float4 xv = ((const float4*)(g_x + off))[t];
    if (docombine) {
        float4 p0 = ((const float4*)(g_q + off))[t];
        float4 p1 = ((const float4*)(g_k + off))[t];
        xv.x += p0.x + p1.x; xv.y += p0.y + p1.y;
        xv.z += p0.z + p1.z; xv.w += p0.w + p1.w;
        ((float4*)(g_x + off))[t] = xv;
    }
    float l0 = lambdas[layer*2 + 0];
    float l1 = lambdas[layer*2 + 1];
    float4 x0v = ((const float4*)(g_x0 + off))[t];
    float4 a;
    a.x = l0*xv.x + l1*x0v.x; a.y = l0*xv.y + l1*x0v.y;
    a.z = l0*xv.z + l1*x0v.z; a.w = l0*xv.w + l1*x0v.w;
    ((float4*)(g_xl + off))[t] = a;
    float r = block_rsqrt_mean_sq(a, sred, t);
    a.x *= r; a.y *= r; a.z *= r; a.w *= r;
    write_ab_split(row, t, a);
}

// after Wo split-K: x = q+k+xl ; ab = split(rms(x))
__global__ __launch_bounds__(256) void fused_mid_kernel() {
    __shared__ float sred[8];
    int row = blockIdx.x;
    int t = threadIdx.x;
    size_t off = (size_t)row * D;
    float4 p0 = ((const float4*)(g_q  + off))[t];
    float4 p1 = ((const float4*)(g_k  + off))[t];
    float4 rr = ((const float4*)(g_xl + off))[t];
    float4 xv;
    xv.x = rr.x + p0.x + p1.x; xv.y = rr.y + p0.y + p1.y;
    xv.z = rr.z + p0.z + p1.z; xv.w = rr.w + p0.w + p1.w;
    ((float4*)(g_x + off))[t] = xv;
    float r = block_rsqrt_mean_sq(xv, sred, t);
    xv.x *= r; xv.y *= r; xv.z *= r; xv.w *= r;
    write_ab_split(row, t, xv);
}

// final: out = rms(q+k+x)
__global__ __launch_bounds__(256) void final_kernel(float* __restrict__ out) {
    __shared__ float sred[8];
    int row = blockIdx.x;
    int t = threadIdx.x;
    size_t off = (size_t)row * D;
    float4 p0 = ((const float4*)(g_q + off))[t];
    float4 p1 = ((const float4*)(g_k + off))[t];
    float4 rr = ((const float4*)(g_x + off))[t];
    float4 xv;
    xv.x = rr.x + p0.x + p1.x; xv.y = rr.y + p0.y + p1.y;
    xv.z = rr.z + p0.z + p1.z; xv.w = rr.w + p0.w + p1.w;
    float r = block_rsqrt_mean_sq(xv, sred, t);
    xv.x *= r; xv.y *= r; xv.z *= r; xv.w *= r;
    ((float4*)(out + off))[t] = xv;
}

__global__ __launch_bounds__(512) void qkrope_kernel() {
    int t = blockIdx.x;
    int h = threadIdx.y;
    int j = threadIdx.x;
    float c  = g_ropec[t * 32 + j];
    float sn = g_ropes[t * 32 + j];
    #pragma unroll
    for (int which = 0; which < 2; which++) {
        float* p = (which ? g_k : g_q) + (size_t)t * D + h * HD;
        float a = p[j];
        float b = p[j + 32];
        float ss = a*a + b*b;
        #pragma unroll
        for (int o = 16; o > 0; o >>= 1) ss += __shfl_xor_sync(0xffffffffu, ss, o);
        float r = rsqrtf(ss * (1.0f/64.0f) + EPS);
        a *= r; b *= r;
        p[j]      =  a*c + b*sn;
        p[j + 32] = -a*sn + b*c;
    }
}

// ---------------- attention: range-limited, 8 q x 1 head / block ----------------
#define MQ 8
#define SCPAD 1028
__global__ __launch_bounds__(256) void attn_kernel() {
    __shared__ float qs[MQ][HD];
    __shared__ float sc[MQ][SCPAD];
    __shared__ float red[MQ][4][HD];
    __shared__ float s_sum[MQ];

    int h  = blockIdx.y;
    int q0 = blockIdx.x * MQ;
    int tid = threadIdx.x;

    if (tid < 128) {
        int mq = tid >> 4;
        int c  = tid & 15;
        ((float4*)qs[mq])[c] = ((const float4*)(g_q + (size_t)(q0 + mq) * D + h * HD))[c];
    }
    __syncthreads();

    const int kmax = q0 + MQ - 1;
    const int k0   = g_kstart[q0] & ~3;
    const int klen = kmax - k0 + 1;          // multiple of 4
    const int kpad = k0 + klen;              // == kmax+1

    const float SCL = 0.125f * 1.4426950408889634f;

    for (int k = k0 + tid; k < kpad; k += 256) {
        float4 kr[16];
        const float4* kp = (const float4*)(g_k + (size_t)k * D + h * HD);
        #pragma unroll
        for (int c = 0; c < 16; c++) kr[c] = kp[c];
        #pragma unroll
        for (int mq = 0; mq < MQ; mq++) {
            const float4* qp = (const float4*)qs[mq];
            float acc = 0.f;
            #pragma unroll
            for (int c = 0; c < 16; c++) {
                float4 qv = qp[c];
                acc += qv.x*kr[c].x + qv.y*kr[c].y + qv.z*kr[c].z + qv.w*kr[c].w;
            }
            bool ok = (g_mask[q0 + mq][k >> 5] >> (k & 31)) & 1u;
            sc[mq][k] = ok ? acc * SCL : -1e30f;
        }
    }
    __syncthreads();

    {
        int w = tid >> 5, lane = tid & 31;
        int mq = w;
        float m = -1e30f;
        for (int k = k0 + lane; k <= kmax; k += 32) m = fmaxf(m, sc[mq][k]);
        #pragma unroll
        for (int o = 16; o > 0; o >>= 1) m = fmaxf(m, __shfl_xor_sync(0xffffffffu, m, o));
        float ssum = 0.f;
        for (int k = k0 + lane; k <= kmax; k += 32) {
            float e = exp2f(sc[mq][k] - m);
            sc[mq][k] = e;
            ssum += e;
        }
        #pragma unroll
        for (int o = 16; o > 0; o >>= 1) ssum += __shfl_xor_sync(0xffffffffu, ssum, o);
        if (lane == 0) s_sum[mq] = ssum;
    }
    __syncthreads();

    {
        int d = tid & 63;
        int qtr = tid >> 6;
        float yacc[MQ];
        #pragma unroll
        for (int mq = 0; mq < MQ; mq++) yacc[mq] = 0.f;
        int qlen = ((klen + 15) >> 4) << 2;
        int kb = k0 + qtr * qlen;
        int ke = kb + qlen;
        for (int k = kb; k < ke && k < kpad; k += 4) {
            float v0 = g_v[(size_t)(k+0) * D + h * HD + d];
            float v1 = g_v[(size_t)(k+1) * D + h * HD + d];
            float v2 = g_v[(size_t)(k+2) * D + h * HD + d];
            float v3 = g_v[(size_t)(k+3) * D + h * HD + d];
            #pragma unroll
            for (int mq = 0; mq < MQ; mq++) {
                float4 p = ((const float4*)sc[mq])[k >> 2];
                yacc[mq] += p.x*v0 + p.y*v1 + p.z*v2 + p.w*v3;
            }
        }
        #pragma unroll
        for (int mq = 0; mq < MQ; mq++) red[mq][qtr][d] = yacc[mq];
        __syncthreads();
        if (qtr == 0) {
            #pragma unroll
            for (int mq = 0; mq < MQ; mq++) {
                float val = (red[mq][0][d] + red[mq][1][d] + red[mq][2][d] + red[mq][3][d])
                            / s_sum[mq];
                int row = q0 + mq, c = h * HD + d;
                __nv_bfloat16 hi, lo;
                split_bf16(val, hi, lo);
                g_ab[(size_t)row * 3072 + c]        = hi;
                g_ab[(size_t)row * 3072 + 1024 + c] = hi;
                g_ab[(size_t)row * 3072 + 2048 + c] = lo;
            }
        }
    }
}

// ================= host orchestration =================
extern "C" void kernel_launch(void* const* d_in, const int* in_sizes, int n_in,
                              void* d_out, int out_size) {
    const float* xin     = (const float*)d_in[0];
    const float* Wq      = (const float*)d_in[1];
    const float* Wk      = (const float*)d_in[2];
    const float* Wv      = (const float*)d_in[3];
    const float* Wo      = (const float*)d_in[4];
    const float* lamb    = (const float*)d_in[5];
    const float* lambdas = (const float*)d_in[6];
    const float* Wfc     = (const float*)d_in[7];
    const float* Wp      = (const float*)d_in[8];
    const int*   levels  = (const int*)d_in[9];
    const int*   sample  = (const int*)d_in[10];
    float* out = (float*)d_out;

    cudaFuncSetAttribute(tc_gemm, cudaFuncAttributeMaxDynamicSharedMemorySize, GSMEM);

    void *pq, *pk, *pv;
    void *pwqkvb, *pwob, *pwfcb, *pwpb, *pab, *phb;
    cudaGetSymbolAddress(&pq,  g_q);
    cudaGetSymbolAddress(&pk,  g_k);
    cudaGetSymbolAddress(&pv,  g_v);
    cudaGetSymbolAddress(&pwqkvb, g_wqkvb);
    cudaGetSymbolAddress(&pwob,   g_wob);
    cudaGetSymbolAddress(&pwfcb,  g_wfcb);
    cudaGetSymbolAddress(&pwpb,   g_wpb);
    cudaGetSymbolAddress(&pab,    g_ab);
    cudaGetSymbolAddress(&phb,    g_hb);

    // weight conversions (every launch; deterministic)
    conv_qkv_kernel<<<NL * 3072 * 256 / 256, 256>>>(Wq, Wk, Wv);
    conv_kernel<<<(NL * 1024 * 1024 / 4) / 256, 256>>>(Wo,  (__nv_bfloat16*)pwob,  1024);
    conv_kernel<<<(NL * 4096 * 1024 / 4) / 256, 256>>>(Wfc, (__nv_bfloat16*)pwfcb, 1024);
    conv_kernel<<<(NL * 1024 * 4096 / 4) / 256, 256>>>(Wp,  (__nv_bfloat16*)pwpb,  4096);

    prefix_kernel<<<1, 32>>>(levels);
    mask_kernel<<<S, 32>>>(levels, sample);
    kstart_kernel<<<(S + 255) / 256, 256>>>(sample);
    rope_table_kernel<<<S, 32>>>();

    rms_init_kernel<<<S, 256>>>(xin);

    for (int l = 0; l < NL; l++) {
        // [combine Wp partials if l>0] + lerp + rms + split -> ab
        fused_top_kernel<<<S, 256>>>(lambdas, l, l > 0 ? 1 : 0);

        // fused QKV GEMM with fused v-mix in epilogue (192 CTAs, single wave @2/SM)
        tc_gemm<<<dim3(3072/128, S/128, 1), 256, GSMEM>>>(
            (const __nv_bfloat16*)pab, (const __nv_bfloat16*)pwqkvb + (size_t)l*3072*3072,
            (float*)pq, (float*)pk, (float*)pv, S, 3072, 3072, 3072, 3072, 0, 3, lamb, l);

        qkrope_kernel<<<S, dim3(32, 16)>>>();
        attn_kernel<<<dim3(S / MQ, H), 256>>>();   // writes g_ab (split y)

        // y @ Wo^T : split-K=2 merged in one launch (gridDim.z=2 -> 128 CTAs)
        tc_gemm<<<dim3(8, 8, 2), 256, GSMEM>>>(
            (const __nv_bfloat16*)pab, (const __nv_bfloat16*)pwob + (size_t)l*1024*3072,
            (float*)pq, (float*)pk, nullptr, S, 1024, 1536, 3072, 3072, 1536, 0, nullptr, 0);

        // x = xl + partials ; ab = split(rms(x))
        fused_mid_kernel<<<S, 256>>>();

        // hb = split(relu(ab @ Wfc^T)^2)   (256 CTAs, single wave @2/SM)
        tc_gemm<<<dim3(4096/128, S/128, 1), 256, GSMEM>>>(
            (const __nv_bfloat16*)pab, (const __nv_bfloat16*)pwfcb + (size_t)l*4096*3072,
            (float*)phb, nullptr, nullptr, S, 4096, 3072, 3072, 3072, 0, 4, nullptr, 0);

        // hb @ Wp^T : split-K=2 merged
        tc_gemm<<<dim3(8, 8, 2), 256, GSMEM>>>(
            (const __nv_bfloat16*)phb, (const __nv_bfloat16*)pwpb + (size_t)l*1024*12288,
            (float*)pq, (float*)pk, nullptr, S, 1024, 6144, 12288, 12288, 6144, 0, nullptr, 0);
    }

    // out = rms(x + Wp partials)
    final_kernel<<<S, 256>>>(out);
}